// round 11
// baseline (speedup 1.0000x reference)
#include <cuda_runtime.h>
#include <cuda_bf16.h>
#include <math.h>
#include <stdint.h>

#define BB 8

// padded pixel slabs
#define PXS1 2916      // 54*54
#define PXS2 11236     // 106*106
#define NPX1T 23584    // 8*2916 + 256 margin
#define NPX2T 90144    // 8*11236 + 256 margin

// ---- device scratch ----
__device__ __nv_bfloat16 g_up1h[(size_t)NPX1T*512];
__device__ __nv_bfloat16 g_up1l[(size_t)NPX1T*512];
__device__ __nv_bfloat16 g_up2h[(size_t)NPX2T*512];
__device__ __nv_bfloat16 g_up2l[(size_t)NPX2T*512];
__device__ float g_r1p[(size_t)BB*512*PXS1];    // conv1 out, padded NCHW
__device__ float g_r2 [(size_t)BB*256*104*104]; // conv2 out, dense NCHW
__device__ __nv_bfloat16 g_w1p[9*512*512*2];    // [cc][ocblk] contiguous 36864-elem blocks
__device__ __nv_bfloat16 g_w2p[9*512*256*2];
__device__ float g_wb [BB*2305];
__device__ float g_effw[BB*256*5*9];
__device__ float g_beta[BB*5*9];
__device__ float g_s1[512], g_o1[512], g_s2[256], g_o2[256];

// ---- BN fold ----
__global__ void bnprep_kernel(const float* __restrict__ g1,const float* __restrict__ b1,
                              const float* __restrict__ m1,const float* __restrict__ v1,
                              const float* __restrict__ g2,const float* __restrict__ b2,
                              const float* __restrict__ m2,const float* __restrict__ v2){
  int i = threadIdx.x;
  if (i < 512){ float s = g1[i]*rsqrtf(v1[i]+1e-5f); g_s1[i]=s; g_o1[i]=b1[i]-m1[i]*s; }
  if (i < 256){ float s = g2[i]*rsqrtf(v2[i]+1e-5f); g_s2[i]=s; g_o2[i]=b2[i]-m2[i]*s; }
}

// ---- weight prep: fp32 [OC][512][3][3] -> bf16 hi/lo, pre-swizzled linear blocks
__global__ void prep_w_kernel(const float* __restrict__ w, __nv_bfloat16* __restrict__ dst,
                              int COUT, int NOCB){
  int idx = blockIdx.x*256 + threadIdx.x;
  if (idx >= COUT*512*9) return;
  int oc = idx / (512*9); int rem = idx % (512*9); int ci = rem/9; int tap = rem%9;
  float v = w[idx];
  __nv_bfloat16 h = __float2bfloat16(v);
  __nv_bfloat16 l = __float2bfloat16(v - __bfloat162float(h));
  int ocblk = oc>>7, ocl = oc&127;
  int cc = ci>>4, cil = ci&15;
  int chunk = (ocl*2 + (cil>>3)) ^ ((ocl>>2)&1);
  size_t base = (size_t)(cc*NOCB + ocblk)*36864 + tap*4096 + chunk*8 + (cil&7);
  dst[base] = h;           // hl=0
  dst[base + 2048] = l;    // hl=1
}

// ---- tiled transpose bilinear 2x upsample: NCHW fp32 -> NHWC-padded bf16 hi/lo
__global__ __launch_bounds__(256)
void up2x_t_kernel(const float* __restrict__ in, int Hin, int rowStr, int chanSlab, int inOff,
                   __nv_bfloat16* __restrict__ oh, __nv_bfloat16* __restrict__ ol,
                   int WP, int pxSlab, int ntx){
  __shared__ float sp[16*361];   // [c][18 rows x stride 20], c-stride 361 (conflict-free)
  int tx = blockIdx.x % ntx, ty = blockIdx.x / ntx;
  int cg = blockIdx.y, b = blockIdx.z;
  int x0o = tx*32, y0o = ty*32;
  int x0i = (x0o>>1) - 1, y0i = (y0o>>1) - 1;
  int tid = threadIdx.x;
  const float* pin = in + (size_t)(b*512 + cg*16)*chanSlab + inOff;
  for (int i = tid; i < 16*324; i += 256){
    int c = i / 324; int rem = i - c*324; int ry = rem/18, rx = rem - ry*18;
    int gy = min(max(y0i+ry,0),Hin-1);
    int gx = min(max(x0i+rx,0),Hin-1);
    sp[c*361 + ry*20 + rx] = pin[(size_t)c*chanSlab + gy*rowStr + gx];
  }
  __syncthreads();
  int c = tid & 15;
  int Hout = Hin*2;
  int cglob = cg*16 + c;
  for (int p = tid >> 4; p < 1024; p += 16){
    int py = p >> 5, px = p & 31;
    int yo = y0o + py, xo = x0o + px;
    if (yo >= Hout || xo >= Hout) continue;
    int r0 = (py>>1) + (py&1), q0 = (px>>1) + (px&1);
    float wy0 = (py&1) ? 0.75f : 0.25f;
    float wx0 = (px&1) ? 0.75f : 0.25f;
    float wy1 = 1.f - wy0, wx1 = 1.f - wx0;
    const float* s0 = &sp[c*361 + r0*20 + q0];
    float v = wy0*(wx0*s0[0] + wx1*s0[1]) + wy1*(wx0*s0[20] + wx1*s0[21]);
    __nv_bfloat16 h = __float2bfloat16(v);
    __nv_bfloat16 l = __float2bfloat16(v - __bfloat162float(h));
    size_t opix = (size_t)b*pxSlab + (size_t)(yo+1)*WP + (xo+1);
    oh[opix*512 + cglob] = h;
    ol[opix*512 + cglob] = l;
  }
}

#define MMA16816(d, a, b0, b1) \
  asm volatile("mma.sync.aligned.m16n8k16.row.col.f32.bf16.bf16.f32 " \
               "{%0,%1,%2,%3},{%4,%5,%6,%7},{%8,%9},{%0,%1,%2,%3};\n" \
               : "+f"(d[0]),"+f"(d[1]),"+f"(d[2]),"+f"(d[3]) \
               : "r"(a[0]),"r"(a[1]),"r"(a[2]),"r"(a[3]),"r"(b0),"r"(b1))

#define LDSMX4(r0,r1,r2,r3,addr) \
  asm volatile("ldmatrix.sync.aligned.m8n8.x4.shared.b16 {%0,%1,%2,%3}, [%4];" \
               : "=r"(r0),"=r"(r1),"=r"(r2),"=r"(r3) : "r"(addr))

#define CPA16(dst, src) \
  asm volatile("cp.async.cg.shared.global [%0], [%1], 16;" :: "r"(dst), "l"(src))
#define CPCOMMIT asm volatile("cp.async.commit_group;" ::: "memory")
#define CPWAIT0  asm volatile("cp.async.wait_group 0;" ::: "memory")

// ---- implicit-GEMM 3x3 conv via mma.sync bf16 hi/lo (3 passes)
// Block: 256 thr = 8 warps (2M x 4N), tile M=128 oc, N=192 px, K-stage = 16ch x 9 taps.
// Double-buffered smem stages AND double-buffered tap fragments.
template<int WP, int COUT, int NOCB, bool MASK>
__global__ __launch_bounds__(256,1)
void conv3x3_mma(const __nv_bfloat16* __restrict__ acth, const __nv_bfloat16* __restrict__ actl,
                 const __nv_bfloat16* __restrict__ wp, const float* __restrict__ scale,
                 const float* __restrict__ offs, float* __restrict__ out){
  constexpr int PXS  = WP*WP;
  constexpr int HALO = WP + 2;
  constexpr int NPX  = 192 + 2*HALO;
  constexpr int ABYTES = 73728;                 // 9 taps x 2 hl x 128 oc x 32B
  constexpr int SSTRIDE = ABYTES + NPX*64;      // + B: 2 hl x NPX x 32B

  extern __shared__ char smraw[];
  uint32_t sbase = (uint32_t)__cvta_generic_to_shared(smraw);

  int tid = threadIdx.x;
  int warp = tid >> 5, lane = tid & 31;
  int g = lane >> 2, t = lane & 3;
  int n0 = WP + blockIdx.x*192;
  int ocblk = blockIdx.y;
  int b = blockIdx.z;
  long long imgpx = (long long)b*PXS;

  int m0  = (warp >> 2)*64;
  int pxb = (warp & 3)*48;

  // lane constants for ldmatrix
  int aoc   = (lane & 7) + (lane & 8);
  int ahalf = lane >> 4;
  uint32_t a_lane_off = (uint32_t)(((((2*aoc + ahalf) ^ ((aoc>>2)&1))) << 4) + m0*32);
  int brow_l = pxb + (lane & 7) + ((lane >> 4) << 3);
  int bhalf  = (lane >> 3) & 1;

  const char* wgbase = (const char*)wp + (size_t)ocblk*73728;
  const char* gah = (const char*)acth;
  const char* gal = (const char*)actl;

  float acc[4][6][4];
  #pragma unroll
  for (int i=0;i<4;i++)
    #pragma unroll
    for (int j=0;j<6;j++)
      #pragma unroll
      for (int k=0;k<4;k++) acc[i][j][k]=0.f;

  auto load_stage = [&](int cc, int soff){
    // A: weights, linear pre-swizzled 73728B block
    const char* srcA = wgbase + (size_t)cc*(NOCB*73728);
    uint32_t abase = sbase + soff;
    #pragma unroll
    for (int it = 0; it < 18; it++){
      int idx = (tid + it*256) << 4;
      CPA16(abase + idx, srcA + idx);
    }
    // B: activations, NPX*4 x 16B chunks
    for (int idx = tid; idx < NPX*4; idx += 256){
      int hl = idx / (NPX*2); int rem = idx - hl*(NPX*2); int px = rem >> 1;
      const char* src = (hl ? gal : gah)
                      + (size_t)(imgpx + n0 - HALO + px)*1024 + cc*32 + (rem & 1)*16;
      uint32_t dst = sbase + soff + ABYTES + hl*(NPX*32) + ((rem ^ ((px>>2)&1)) << 4);
      CPA16(dst, src);
    }
    CPCOMMIT;
  };

  auto compute = [&](int soff){
    uint32_t aA = sbase + soff + a_lane_off;
    uint32_t bB = sbase + soff + ABYTES;
    uint32_t ah[2][4][4], al[2][4][4], bh[2][6][2], bl[2][6][2];

    auto ldfrag = [&](int tap, int buf){
      uint32_t tA = aA + tap*8192;
      #pragma unroll
      for (int mf=0; mf<4; mf++){
        LDSMX4(ah[buf][mf][0],ah[buf][mf][1],ah[buf][mf][2],ah[buf][mf][3], tA + mf*512);
        LDSMX4(al[buf][mf][0],al[buf][mf][1],al[buf][mf][2],al[buf][mf][3], tA + 4096 + mf*512);
      }
      int toff = (tap/3 - 1)*WP + (tap%3 - 1);
      int row0 = HALO + toff + brow_l;
      #pragma unroll
      for (int j=0; j<3; j++){
        int r = row0 + j*16;
        uint32_t u = (uint32_t)((2*r + bhalf) ^ ((r>>2)&1));
        uint32_t ha = bB + (u << 4);
        LDSMX4(bh[buf][2*j][0], bh[buf][2*j][1], bh[buf][2*j+1][0], bh[buf][2*j+1][1], ha);
        LDSMX4(bl[buf][2*j][0], bl[buf][2*j][1], bl[buf][2*j+1][0], bl[buf][2*j+1][1], ha + NPX*32);
      }
    };

    ldfrag(0, 0);
    #pragma unroll
    for (int tap = 0; tap < 9; tap++){
      int cur = tap & 1;
      if (tap < 8) ldfrag(tap+1, cur^1);
      #pragma unroll
      for (int mf=0; mf<4; mf++)
        #pragma unroll
        for (int nf=0; nf<6; nf++){
          MMA16816(acc[mf][nf], ah[cur][mf], bh[cur][nf][0], bh[cur][nf][1]);
          MMA16816(acc[mf][nf], ah[cur][mf], bl[cur][nf][0], bl[cur][nf][1]);
          MMA16816(acc[mf][nf], al[cur][mf], bh[cur][nf][0], bh[cur][nf][1]);
        }
    }
  };

  load_stage(0, 0);
  for (int cc = 0; cc < 32; cc++){
    CPWAIT0;
    __syncthreads();
    if (cc + 1 < 32) load_stage(cc+1, ((cc+1)&1)*SSTRIDE);
    compute((cc&1)*SSTRIDE);
  }

  // epilogue: BN + ReLU
  #pragma unroll
  for (int mf=0; mf<4; mf++){
    int ocA = ocblk*128 + m0 + mf*16 + g;
    float s0 = scale[ocA],   o0 = offs[ocA];
    float s1 = scale[ocA+8], o1 = offs[ocA+8];
    #pragma unroll
    for (int nf=0; nf<6; nf++){
      int pix = n0 + pxb + nf*8 + t*2;
      float v00 = fmaf(acc[mf][nf][0], s0, o0); v00 = v00 > 0.f ? v00 : 0.f;
      float v01 = fmaf(acc[mf][nf][1], s0, o0); v01 = v01 > 0.f ? v01 : 0.f;
      float v10 = fmaf(acc[mf][nf][2], s1, o1); v10 = v10 > 0.f ? v10 : 0.f;
      float v11 = fmaf(acc[mf][nf][3], s1, o1); v11 = v11 > 0.f ? v11 : 0.f;
      if (!MASK){
        if (pix < PXS - 1){
          float2* p0 = (float2*)&out[ (size_t)(b*COUT + ocA  )*PXS + pix ];
          float2* p1 = (float2*)&out[ (size_t)(b*COUT + ocA+8)*PXS + pix ];
          *p0 = make_float2(v00, v01);
          *p1 = make_float2(v10, v11);
        }
      } else {
        #pragma unroll
        for (int e=0; e<2; e++){
          int pp = pix + e;
          int y = pp / WP, x = pp - y*WP;
          if (y >= 1 && y <= 104 && x >= 1 && x <= 104){
            size_t d = ((size_t)(b*COUT + ocA)*104 + (y-1))*104 + (x-1);
            out[d] = e ? v01 : v00;
            out[d + (size_t)8*104*104] = e ? v11 : v10;  // oc+8 row
          }
        }
      }
    }
  }
}

// ---- wb = word @ txt_w.T + txt_b ----
__global__ void wb_kernel(const float* __restrict__ word, const float* __restrict__ txt_w,
                          const float* __restrict__ txt_b){
  int j = blockIdx.x;
  int warp = threadIdx.x >> 5, lane = threadIdx.x & 31;
  const float* wrow = word + warp*1024;
  const float* trow = txt_w + (size_t)j*1024;
  float s = 0.f;
  for (int k = lane; k < 1024; k += 32) s = fmaf(wrow[k], trow[k], s);
  #pragma unroll
  for (int off=16; off; off>>=1) s += __shfl_down_sync(0xffffffffu, s, off);
  if (lane == 0) g_wb[warp*2305 + j] = s + txt_b[j];
}

// ---- effW / beta: one block per (b, task); w3 value reused across all 9 taps ----
__global__ void effw_kernel(const float* __restrict__ w3, const float* __restrict__ b3){
  int t = blockIdx.x % 5, b = blockIdx.x / 5;
  int tid = threadIdx.x;
  __shared__ float dw[2304];
  __shared__ float sb3[256];
  __shared__ float red[256];
  for (int i = tid; i < 2304; i += 256) dw[i] = g_wb[b*2305 + i];
  sb3[tid] = b3[t*256 + tid];
  __syncthreads();
  float acc[9];
  #pragma unroll
  for (int k=0;k<9;k++) acc[k]=0.f;
  for (int c = 0; c < 256; c++){
    float wv = w3[(size_t)(t*256 + c)*256 + tid];
    #pragma unroll
    for (int k=0;k<9;k++) acc[k] = fmaf(dw[c*9+k], wv, acc[k]);
  }
  #pragma unroll
  for (int k=0;k<9;k++)
    g_effw[((size_t)(b*256 + tid)*5 + t)*9 + k] = acc[k];
  for (int k=0;k<9;k++){
    red[tid] = dw[tid*9+k]*sb3[tid];
    __syncthreads();
    for (int s=128;s;s>>=1){ if (tid<s) red[tid]+=red[tid+s]; __syncthreads(); }
    if (tid==0) g_beta[b*45 + t*9 + k] = red[0];
    __syncthreads();
  }
}

// ---- fused (1x1 conv + dynamic 3x3 conv) ----
__global__ __launch_bounds__(256)
void dynconv_kernel(float* __restrict__ out){
  constexpr int HW = 104;
  __shared__ float s_in[8*34*35];
  __shared__ float s_w[8*45];
  __shared__ float s_beta[45];
  int tid = threadIdx.x;
  int tile = blockIdx.x;
  int tx = tile & 3, ty = tile >> 2;
  int y0 = ty*32, x0 = tx*32;
  int b = blockIdx.y;
  if (tid < 45) s_beta[tid] = g_beta[b*45 + tid];
  int r  = tid >> 3;
  int c0 = (tid & 7) * 4;
  float acc[5][4];
  #pragma unroll
  for (int t=0;t<5;t++)
    #pragma unroll
    for (int p=0;p<4;p++) acc[t][p]=0.f;

  for (int cb = 0; cb < 32; cb++){
    for (int idx = tid; idx < 8*34*34; idx += 256){
      int ci  = idx / 1156;
      int rem = idx - ci*1156;
      int ry = rem / 34, rx = rem - ry*34;
      int gy = y0-1+ry, gx = x0-1+rx;
      float v = 0.f;
      if (gy>=0 && gy<HW && gx>=0 && gx<HW)
        v = g_r2[((size_t)(b*256 + cb*8 + ci)*HW + gy)*HW + gx];
      s_in[(ci*34+ry)*35 + rx] = v;
    }
    for (int idx = tid; idx < 360; idx += 256)
      s_w[idx] = g_effw[(size_t)(b*256 + cb*8)*45 + idx];
    __syncthreads();
    #pragma unroll
    for (int ci=0;ci<8;ci++){
      #pragma unroll
      for (int ky=0;ky<3;ky++){
        float rowv[6];
        #pragma unroll
        for (int j=0;j<6;j++) rowv[j] = s_in[(ci*34 + r + ky)*35 + c0 + j];
        #pragma unroll
        for (int kx=0;kx<3;kx++){
          #pragma unroll
          for (int t=0;t<5;t++){
            float wv = s_w[ci*45 + t*9 + ky*3 + kx];
            #pragma unroll
            for (int p=0;p<4;p++)
              acc[t][p] = fmaf(wv, rowv[p+kx], acc[t][p]);
          }
        }
      }
    }
    __syncthreads();
  }
  float dynb = g_wb[b*2305 + 2304];
  int y = y0 + r;
  if (y >= HW) return;
  #pragma unroll
  for (int p=0;p<4;p++){
    int x = x0 + c0 + p;
    if (x >= HW) continue;
    #pragma unroll
    for (int t=0;t<5;t++){
      float v = acc[t][p] + dynb;
      #pragma unroll
      for (int ky=0;ky<3;ky++){
        int yy = y+ky-1;
        if (yy < 0 || yy >= HW) continue;
        #pragma unroll
        for (int kx=0;kx<3;kx++){
          int xx = x+kx-1;
          if (xx < 0 || xx >= HW) continue;
          v += s_beta[t*9 + ky*3 + kx];
        }
      }
      out[((size_t)(t*BB + b)*HW + y)*HW + x] = v;
    }
  }
}

extern "C" void kernel_launch(void* const* d_in, const int* in_sizes, int n_in,
                              void* d_out, int out_size){
  const float* x    = (const float*)d_in[0];
  const float* word = (const float*)d_in[1];
  const float* w1   = (const float*)d_in[2];
  const float* bn1g = (const float*)d_in[3];
  const float* bn1b = (const float*)d_in[4];
  const float* bn1m = (const float*)d_in[5];
  const float* bn1v = (const float*)d_in[6];
  const float* w2   = (const float*)d_in[7];
  const float* bn2g = (const float*)d_in[8];
  const float* bn2b = (const float*)d_in[9];
  const float* bn2m = (const float*)d_in[10];
  const float* bn2v = (const float*)d_in[11];
  const float* w3   = (const float*)d_in[12];
  const float* b3   = (const float*)d_in[13];
  const float* txtw = (const float*)d_in[14];
  const float* txtb = (const float*)d_in[15];
  float* out = (float*)d_out;

  __nv_bfloat16 *up1h, *up1l, *up2h, *up2l, *w1p, *w2p;
  float *r1p, *r2, *s1, *o1, *s2, *o2;
  cudaGetSymbolAddress((void**)&up1h, g_up1h);
  cudaGetSymbolAddress((void**)&up1l, g_up1l);
  cudaGetSymbolAddress((void**)&up2h, g_up2h);
  cudaGetSymbolAddress((void**)&up2l, g_up2l);
  cudaGetSymbolAddress((void**)&w1p,  g_w1p);
  cudaGetSymbolAddress((void**)&w2p,  g_w2p);
  cudaGetSymbolAddress((void**)&r1p,  g_r1p);
  cudaGetSymbolAddress((void**)&r2,   g_r2);
  cudaGetSymbolAddress((void**)&s1,   g_s1);
  cudaGetSymbolAddress((void**)&o1,   g_o1);
  cudaGetSymbolAddress((void**)&s2,   g_s2);
  cudaGetSymbolAddress((void**)&o2,   g_o2);
  // margin-adjusted activation bases (64-pixel front margin)
  __nv_bfloat16* a1h = up1h + (size_t)64*512;
  __nv_bfloat16* a1l = up1l + (size_t)64*512;
  __nv_bfloat16* a2h = up2h + (size_t)64*512;
  __nv_bfloat16* a2l = up2l + (size_t)64*512;

  const int SMEM1 = 2*(73728 + 304*64);   // 186368
  const int SMEM2 = 2*(73728 + 408*64);   // 199680
  cudaFuncSetAttribute(conv3x3_mma<54,512,4,false>,
                       cudaFuncAttributeMaxDynamicSharedMemorySize, SMEM1);
  cudaFuncSetAttribute(conv3x3_mma<106,256,2,true>,
                       cudaFuncAttributeMaxDynamicSharedMemorySize, SMEM2);

  // ordered so conv1 is the 4th launch (profile capture index)
  prep_w_kernel<<<(512*512*9+255)/256,256>>>(w1, w1p, 512, 4);
  // up2x #1: 26 -> 52, into 54-padded NHWC bf16 hi/lo
  up2x_t_kernel<<<dim3(4, 32, BB),256>>>(x, 26, 26, 676, 0, a1h, a1l, 54, PXS1, 2);
  bnprep_kernel<<<1,512>>>(bn1g,bn1b,bn1m,bn1v,bn2g,bn2b,bn2m,bn2v);
  conv3x3_mma<54,512,4,false><<<dim3(15,4,BB),256,SMEM1>>>(a1h, a1l, w1p, s1, o1, r1p);
  prep_w_kernel<<<(256*512*9+255)/256,256>>>(w2, w2p, 256, 2);
  wb_kernel<<<2305,256>>>(word, txtw, txtb);
  effw_kernel<<<40,256>>>(w3, b3);
  // up2x #2: 52 -> 104, reading r1p interior (54-padded), into 106-padded NHWC
  up2x_t_kernel<<<dim3(16, 32, BB),256>>>(r1p, 52, 54, 2916, 55, a2h, a2l, 106, PXS2, 4);
  conv3x3_mma<106,256,2,true><<<dim3(58,2,BB),256,SMEM2>>>(a2h, a2l, w2p, s2, o2, r2);
  dynconv_kernel<<<dim3(16,BB),256>>>(out);
}

// round 12
// speedup vs baseline: 1.0464x; 1.0464x over previous
#include <cuda_runtime.h>
#include <cuda_bf16.h>
#include <math.h>
#include <stdint.h>

#define BB 8

// padded pixel slabs
#define PXS1 2916      // 54*54
#define PXS2 11236     // 106*106
#define NPX1T 23584    // 8*2916 + 256 margin
#define NPX2T 90144    // 8*11236 + 256 margin

// ---- device scratch ----
__device__ __nv_bfloat16 g_up1h[(size_t)NPX1T*512];
__device__ __nv_bfloat16 g_up1l[(size_t)NPX1T*512];
__device__ __nv_bfloat16 g_up2h[(size_t)NPX2T*512];
__device__ __nv_bfloat16 g_up2l[(size_t)NPX2T*512];
__device__ float g_r1p[(size_t)BB*512*PXS1];    // conv1 out, padded NCHW
__device__ float g_r2 [(size_t)BB*256*104*104]; // conv2 out, dense NCHW
__device__ __nv_bfloat16 g_w1p[9*512*512*2];    // [cc][ocblk] contiguous 36864-elem blocks
__device__ __nv_bfloat16 g_w2p[9*512*256*2];
__device__ float g_wb [BB*2305];
__device__ float g_effw[BB*256*5*9];
__device__ float g_beta[BB*5*9];
__device__ float g_s1[512], g_o1[512], g_s2[256], g_o2[256];

// ---- BN fold ----
__global__ void bnprep_kernel(const float* __restrict__ g1,const float* __restrict__ b1,
                              const float* __restrict__ m1,const float* __restrict__ v1,
                              const float* __restrict__ g2,const float* __restrict__ b2,
                              const float* __restrict__ m2,const float* __restrict__ v2){
  int i = threadIdx.x;
  if (i < 512){ float s = g1[i]*rsqrtf(v1[i]+1e-5f); g_s1[i]=s; g_o1[i]=b1[i]-m1[i]*s; }
  if (i < 256){ float s = g2[i]*rsqrtf(v2[i]+1e-5f); g_s2[i]=s; g_o2[i]=b2[i]-m2[i]*s; }
}

// ---- weight prep: fp32 [OC][512][3][3] -> bf16 hi/lo, pre-swizzled linear blocks
__global__ void prep_w_kernel(const float* __restrict__ w, __nv_bfloat16* __restrict__ dst,
                              int COUT, int NOCB){
  int idx = blockIdx.x*256 + threadIdx.x;
  if (idx >= COUT*512*9) return;
  int oc = idx / (512*9); int rem = idx % (512*9); int ci = rem/9; int tap = rem%9;
  float v = w[idx];
  __nv_bfloat16 h = __float2bfloat16(v);
  __nv_bfloat16 l = __float2bfloat16(v - __bfloat162float(h));
  int ocblk = oc>>7, ocl = oc&127;
  int cc = ci>>4, cil = ci&15;
  int chunk = (ocl*2 + (cil>>3)) ^ ((ocl>>2)&1);
  size_t base = (size_t)(cc*NOCB + ocblk)*36864 + tap*4096 + chunk*8 + (cil&7);
  dst[base] = h;           // hl=0
  dst[base + 2048] = l;    // hl=1
}

// ---- tiled transpose bilinear 2x upsample: NCHW fp32 -> NHWC-padded bf16 hi/lo
__global__ __launch_bounds__(256)
void up2x_t_kernel(const float* __restrict__ in, int Hin, int rowStr, int chanSlab, int inOff,
                   __nv_bfloat16* __restrict__ oh, __nv_bfloat16* __restrict__ ol,
                   int WP, int pxSlab, int ntx){
  __shared__ float sp[16*361];   // [c][18 rows x stride 20], c-stride 361 (conflict-free)
  int tx = blockIdx.x % ntx, ty = blockIdx.x / ntx;
  int cg = blockIdx.y, b = blockIdx.z;
  int x0o = tx*32, y0o = ty*32;
  int x0i = (x0o>>1) - 1, y0i = (y0o>>1) - 1;
  int tid = threadIdx.x;
  const float* pin = in + (size_t)(b*512 + cg*16)*chanSlab + inOff;
  for (int i = tid; i < 16*324; i += 256){
    int c = i / 324; int rem = i - c*324; int ry = rem/18, rx = rem - ry*18;
    int gy = min(max(y0i+ry,0),Hin-1);
    int gx = min(max(x0i+rx,0),Hin-1);
    sp[c*361 + ry*20 + rx] = pin[(size_t)c*chanSlab + gy*rowStr + gx];
  }
  __syncthreads();
  int c = tid & 15;
  int Hout = Hin*2;
  int cglob = cg*16 + c;
  for (int p = tid >> 4; p < 1024; p += 16){
    int py = p >> 5, px = p & 31;
    int yo = y0o + py, xo = x0o + px;
    if (yo >= Hout || xo >= Hout) continue;
    int r0 = (py>>1) + (py&1), q0 = (px>>1) + (px&1);
    float wy0 = (py&1) ? 0.75f : 0.25f;
    float wx0 = (px&1) ? 0.75f : 0.25f;
    float wy1 = 1.f - wy0, wx1 = 1.f - wx0;
    const float* s0 = &sp[c*361 + r0*20 + q0];
    float v = wy0*(wx0*s0[0] + wx1*s0[1]) + wy1*(wx0*s0[20] + wx1*s0[21]);
    __nv_bfloat16 h = __float2bfloat16(v);
    __nv_bfloat16 l = __float2bfloat16(v - __bfloat162float(h));
    size_t opix = (size_t)b*pxSlab + (size_t)(yo+1)*WP + (xo+1);
    oh[opix*512 + cglob] = h;
    ol[opix*512 + cglob] = l;
  }
}

#define MMA16816(d, a, b0, b1) \
  asm volatile("mma.sync.aligned.m16n8k16.row.col.f32.bf16.bf16.f32 " \
               "{%0,%1,%2,%3},{%4,%5,%6,%7},{%8,%9},{%0,%1,%2,%3};\n" \
               : "+f"(d[0]),"+f"(d[1]),"+f"(d[2]),"+f"(d[3]) \
               : "r"(a[0]),"r"(a[1]),"r"(a[2]),"r"(a[3]),"r"(b0),"r"(b1))

#define LDSMX4(r0,r1,r2,r3,addr) \
  asm volatile("ldmatrix.sync.aligned.m8n8.x4.shared.b16 {%0,%1,%2,%3}, [%4];" \
               : "=r"(r0),"=r"(r1),"=r"(r2),"=r"(r3) : "r"(addr))

#define CPA16(dst, src) \
  asm volatile("cp.async.cg.shared.global [%0], [%1], 16;" :: "r"(dst), "l"(src))
#define CPCOMMIT asm volatile("cp.async.commit_group;" ::: "memory")
#define CPWAIT0  asm volatile("cp.async.wait_group 0;" ::: "memory")

// ---- implicit-GEMM 3x3 conv via mma.sync bf16 hi/lo (3 passes)
// Block: 256 thr = 8 warps (2M x 4N), tile M=128 oc, N=128 px, K-stage = 16ch x 9 taps.
// Double-buffered smem stages AND double-buffered tap fragments.
// Next-stage cp.async issue is interleaved after tap 0's MMA block so the LSU
// issue burst overlaps the tensor-pipe backlog instead of preceding it.
template<int WP, int COUT, int NOCB, bool MASK>
__global__ __launch_bounds__(256,1)
void conv3x3_mma(const __nv_bfloat16* __restrict__ acth, const __nv_bfloat16* __restrict__ actl,
                 const __nv_bfloat16* __restrict__ wp, const float* __restrict__ scale,
                 const float* __restrict__ offs, float* __restrict__ out){
  constexpr int PXS  = WP*WP;
  constexpr int HALO = WP + 2;
  constexpr int NPX  = 128 + 2*HALO;
  constexpr int ABYTES = 73728;                 // 9 taps x 2 hl x 128 oc x 32B
  constexpr int SSTRIDE = ABYTES + NPX*64;      // + B: 2 hl x NPX x 32B

  extern __shared__ char smraw[];
  uint32_t sbase = (uint32_t)__cvta_generic_to_shared(smraw);

  int tid = threadIdx.x;
  int warp = tid >> 5, lane = tid & 31;
  int g = lane >> 2, t = lane & 3;
  int n0 = WP + blockIdx.x*128;
  int ocblk = blockIdx.y;
  int b = blockIdx.z;
  long long imgpx = (long long)b*PXS;

  int m0  = (warp >> 2)*64;
  int pxb = (warp & 3)*32;

  // lane constants for ldmatrix
  int aoc   = (lane & 7) + (lane & 8);
  int ahalf = lane >> 4;
  uint32_t a_lane_off = (uint32_t)(((((2*aoc + ahalf) ^ ((aoc>>2)&1))) << 4) + m0*32);
  int brow_l = pxb + (lane & 7) + ((lane >> 4) << 3);
  int bhalf  = (lane >> 3) & 1;

  const char* wgbase = (const char*)wp + (size_t)ocblk*73728;
  const char* gah = (const char*)acth;
  const char* gal = (const char*)actl;

  float acc[4][4][4];
  #pragma unroll
  for (int i=0;i<4;i++)
    #pragma unroll
    for (int j=0;j<4;j++)
      #pragma unroll
      for (int k=0;k<4;k++) acc[i][j][k]=0.f;

  auto load_stage = [&](int cc, int soff){
    // A: weights, linear pre-swizzled 73728B block
    const char* srcA = wgbase + (size_t)cc*(NOCB*73728);
    uint32_t abase = sbase + soff;
    #pragma unroll
    for (int it = 0; it < 18; it++){
      int idx = (tid + it*256) << 4;
      CPA16(abase + idx, srcA + idx);
    }
    // B: activations, NPX*4 x 16B chunks
    for (int idx = tid; idx < NPX*4; idx += 256){
      int hl = idx / (NPX*2); int rem = idx - hl*(NPX*2); int px = rem >> 1;
      const char* src = (hl ? gal : gah)
                      + (size_t)(imgpx + n0 - HALO + px)*1024 + cc*32 + (rem & 1)*16;
      uint32_t dst = sbase + soff + ABYTES + hl*(NPX*32) + ((rem ^ ((px>>2)&1)) << 4);
      CPA16(dst, src);
    }
    CPCOMMIT;
  };

  // compute current stage; after tap 0's MMA block, issue next stage's loads
  auto compute = [&](int soff, int ncc, int nsoff, bool doload){
    uint32_t aA = sbase + soff + a_lane_off;
    uint32_t bB = sbase + soff + ABYTES;
    uint32_t ah[2][4][4], al[2][4][4], bh[2][4][2], bl[2][4][2];

    auto ldfrag = [&](int tap, int buf){
      uint32_t tA = aA + tap*8192;
      #pragma unroll
      for (int mf=0; mf<4; mf++){
        LDSMX4(ah[buf][mf][0],ah[buf][mf][1],ah[buf][mf][2],ah[buf][mf][3], tA + mf*512);
        LDSMX4(al[buf][mf][0],al[buf][mf][1],al[buf][mf][2],al[buf][mf][3], tA + 4096 + mf*512);
      }
      int toff = (tap/3 - 1)*WP + (tap%3 - 1);
      int row0 = HALO + toff + brow_l;
      #pragma unroll
      for (int j=0; j<2; j++){
        int r = row0 + j*16;
        uint32_t u = (uint32_t)((2*r + bhalf) ^ ((r>>2)&1));
        uint32_t ha = bB + (u << 4);
        LDSMX4(bh[buf][2*j][0], bh[buf][2*j][1], bh[buf][2*j+1][0], bh[buf][2*j+1][1], ha);
        LDSMX4(bl[buf][2*j][0], bl[buf][2*j][1], bl[buf][2*j+1][0], bl[buf][2*j+1][1], ha + NPX*32);
      }
    };

    ldfrag(0, 0);
    #pragma unroll
    for (int tap = 0; tap < 9; tap++){
      int cur = tap & 1;
      if (tap < 8) ldfrag(tap+1, cur^1);
      #pragma unroll
      for (int mf=0; mf<4; mf++)
        #pragma unroll
        for (int nf=0; nf<4; nf++){
          MMA16816(acc[mf][nf], ah[cur][mf], bh[cur][nf][0], bh[cur][nf][1]);
          MMA16816(acc[mf][nf], ah[cur][mf], bl[cur][nf][0], bl[cur][nf][1]);
          MMA16816(acc[mf][nf], al[cur][mf], bh[cur][nf][0], bh[cur][nf][1]);
        }
      if (tap == 0 && doload) load_stage(ncc, nsoff);
    }
  };

  load_stage(0, 0);
  for (int cc = 0; cc < 32; cc++){
    CPWAIT0;
    __syncthreads();
    compute((cc&1)*SSTRIDE, cc+1, ((cc+1)&1)*SSTRIDE, cc+1 < 32);
  }

  // epilogue: BN + ReLU
  #pragma unroll
  for (int mf=0; mf<4; mf++){
    int ocA = ocblk*128 + m0 + mf*16 + g;
    float s0 = scale[ocA],   o0 = offs[ocA];
    float s1 = scale[ocA+8], o1 = offs[ocA+8];
    #pragma unroll
    for (int nf=0; nf<4; nf++){
      int pix = n0 + pxb + nf*8 + t*2;
      float v00 = fmaf(acc[mf][nf][0], s0, o0); v00 = v00 > 0.f ? v00 : 0.f;
      float v01 = fmaf(acc[mf][nf][1], s0, o0); v01 = v01 > 0.f ? v01 : 0.f;
      float v10 = fmaf(acc[mf][nf][2], s1, o1); v10 = v10 > 0.f ? v10 : 0.f;
      float v11 = fmaf(acc[mf][nf][3], s1, o1); v11 = v11 > 0.f ? v11 : 0.f;
      if (!MASK){
        float2* p0 = (float2*)&out[ (size_t)(b*COUT + ocA  )*PXS + pix ];
        float2* p1 = (float2*)&out[ (size_t)(b*COUT + ocA+8)*PXS + pix ];
        *p0 = make_float2(v00, v01);
        *p1 = make_float2(v10, v11);
      } else {
        #pragma unroll
        for (int e=0; e<2; e++){
          int pp = pix + e;
          int y = pp / WP, x = pp - y*WP;
          if (y >= 1 && y <= 104 && x >= 1 && x <= 104){
            size_t d = ((size_t)(b*COUT + ocA)*104 + (y-1))*104 + (x-1);
            out[d] = e ? v01 : v00;
            out[d + (size_t)8*104*104] = e ? v11 : v10;  // oc+8 row
          }
        }
      }
    }
  }
}

// ---- wb = word @ txt_w.T + txt_b ----
__global__ void wb_kernel(const float* __restrict__ word, const float* __restrict__ txt_w,
                          const float* __restrict__ txt_b){
  int j = blockIdx.x;
  int warp = threadIdx.x >> 5, lane = threadIdx.x & 31;
  const float* wrow = word + warp*1024;
  const float* trow = txt_w + (size_t)j*1024;
  float s = 0.f;
  for (int k = lane; k < 1024; k += 32) s = fmaf(wrow[k], trow[k], s);
  #pragma unroll
  for (int off=16; off; off>>=1) s += __shfl_down_sync(0xffffffffu, s, off);
  if (lane == 0) g_wb[warp*2305 + j] = s + txt_b[j];
}

// ---- effW / beta: one block per (b, task); w3 value reused across all 9 taps ----
__global__ void effw_kernel(const float* __restrict__ w3, const float* __restrict__ b3){
  int t = blockIdx.x % 5, b = blockIdx.x / 5;
  int tid = threadIdx.x;
  __shared__ float dw[2304];
  __shared__ float sb3[256];
  __shared__ float red[256];
  for (int i = tid; i < 2304; i += 256) dw[i] = g_wb[b*2305 + i];
  sb3[tid] = b3[t*256 + tid];
  __syncthreads();
  float acc[9];
  #pragma unroll
  for (int k=0;k<9;k++) acc[k]=0.f;
  for (int c = 0; c < 256; c++){
    float wv = w3[(size_t)(t*256 + c)*256 + tid];
    #pragma unroll
    for (int k=0;k<9;k++) acc[k] = fmaf(dw[c*9+k], wv, acc[k]);
  }
  #pragma unroll
  for (int k=0;k<9;k++)
    g_effw[((size_t)(b*256 + tid)*5 + t)*9 + k] = acc[k];
  for (int k=0;k<9;k++){
    red[tid] = dw[tid*9+k]*sb3[tid];
    __syncthreads();
    for (int s=128;s;s>>=1){ if (tid<s) red[tid]+=red[tid+s]; __syncthreads(); }
    if (tid==0) g_beta[b*45 + t*9 + k] = red[0];
    __syncthreads();
  }
}

// ---- fused (1x1 conv + dynamic 3x3 conv) ----
__global__ __launch_bounds__(256)
void dynconv_kernel(float* __restrict__ out){
  constexpr int HW = 104;
  __shared__ float s_in[8*34*35];
  __shared__ float s_w[8*45];
  __shared__ float s_beta[45];
  int tid = threadIdx.x;
  int tile = blockIdx.x;
  int tx = tile & 3, ty = tile >> 2;
  int y0 = ty*32, x0 = tx*32;
  int b = blockIdx.y;
  if (tid < 45) s_beta[tid] = g_beta[b*45 + tid];
  int r  = tid >> 3;
  int c0 = (tid & 7) * 4;
  float acc[5][4];
  #pragma unroll
  for (int t=0;t<5;t++)
    #pragma unroll
    for (int p=0;p<4;p++) acc[t][p]=0.f;

  for (int cb = 0; cb < 32; cb++){
    for (int idx = tid; idx < 8*34*34; idx += 256){
      int ci  = idx / 1156;
      int rem = idx - ci*1156;
      int ry = rem / 34, rx = rem - ry*34;
      int gy = y0-1+ry, gx = x0-1+rx;
      float v = 0.f;
      if (gy>=0 && gy<HW && gx>=0 && gx<HW)
        v = g_r2[((size_t)(b*256 + cb*8 + ci)*HW + gy)*HW + gx];
      s_in[(ci*34+ry)*35 + rx] = v;
    }
    for (int idx = tid; idx < 360; idx += 256)
      s_w[idx] = g_effw[(size_t)(b*256 + cb*8)*45 + idx];
    __syncthreads();
    #pragma unroll
    for (int ci=0;ci<8;ci++){
      #pragma unroll
      for (int ky=0;ky<3;ky++){
        float rowv[6];
        #pragma unroll
        for (int j=0;j<6;j++) rowv[j] = s_in[(ci*34 + r + ky)*35 + c0 + j];
        #pragma unroll
        for (int kx=0;kx<3;kx++){
          #pragma unroll
          for (int t=0;t<5;t++){
            float wv = s_w[ci*45 + t*9 + ky*3 + kx];
            #pragma unroll
            for (int p=0;p<4;p++)
              acc[t][p] = fmaf(wv, rowv[p+kx], acc[t][p]);
          }
        }
      }
    }
    __syncthreads();
  }
  float dynb = g_wb[b*2305 + 2304];
  int y = y0 + r;
  if (y >= HW) return;
  #pragma unroll
  for (int p=0;p<4;p++){
    int x = x0 + c0 + p;
    if (x >= HW) continue;
    #pragma unroll
    for (int t=0;t<5;t++){
      float v = acc[t][p] + dynb;
      #pragma unroll
      for (int ky=0;ky<3;ky++){
        int yy = y+ky-1;
        if (yy < 0 || yy >= HW) continue;
        #pragma unroll
        for (int kx=0;kx<3;kx++){
          int xx = x+kx-1;
          if (xx < 0 || xx >= HW) continue;
          v += s_beta[t*9 + ky*3 + kx];
        }
      }
      out[((size_t)(t*BB + b)*HW + y)*HW + x] = v;
    }
  }
}

extern "C" void kernel_launch(void* const* d_in, const int* in_sizes, int n_in,
                              void* d_out, int out_size){
  const float* x    = (const float*)d_in[0];
  const float* word = (const float*)d_in[1];
  const float* w1   = (const float*)d_in[2];
  const float* bn1g = (const float*)d_in[3];
  const float* bn1b = (const float*)d_in[4];
  const float* bn1m = (const float*)d_in[5];
  const float* bn1v = (const float*)d_in[6];
  const float* w2   = (const float*)d_in[7];
  const float* bn2g = (const float*)d_in[8];
  const float* bn2b = (const float*)d_in[9];
  const float* bn2m = (const float*)d_in[10];
  const float* bn2v = (const float*)d_in[11];
  const float* w3   = (const float*)d_in[12];
  const float* b3   = (const float*)d_in[13];
  const float* txtw = (const float*)d_in[14];
  const float* txtb = (const float*)d_in[15];
  float* out = (float*)d_out;

  __nv_bfloat16 *up1h, *up1l, *up2h, *up2l, *w1p, *w2p;
  float *r1p, *r2, *s1, *o1, *s2, *o2;
  cudaGetSymbolAddress((void**)&up1h, g_up1h);
  cudaGetSymbolAddress((void**)&up1l, g_up1l);
  cudaGetSymbolAddress((void**)&up2h, g_up2h);
  cudaGetSymbolAddress((void**)&up2l, g_up2l);
  cudaGetSymbolAddress((void**)&w1p,  g_w1p);
  cudaGetSymbolAddress((void**)&w2p,  g_w2p);
  cudaGetSymbolAddress((void**)&r1p,  g_r1p);
  cudaGetSymbolAddress((void**)&r2,   g_r2);
  cudaGetSymbolAddress((void**)&s1,   g_s1);
  cudaGetSymbolAddress((void**)&o1,   g_o1);
  cudaGetSymbolAddress((void**)&s2,   g_s2);
  cudaGetSymbolAddress((void**)&o2,   g_o2);
  // margin-adjusted activation bases (64-pixel front margin)
  __nv_bfloat16* a1h = up1h + (size_t)64*512;
  __nv_bfloat16* a1l = up1l + (size_t)64*512;
  __nv_bfloat16* a2h = up2h + (size_t)64*512;
  __nv_bfloat16* a2l = up2l + (size_t)64*512;

  const int SMEM1 = 2*(73728 + 240*64);   // 178176
  const int SMEM2 = 2*(73728 + 344*64);   // 191488
  cudaFuncSetAttribute(conv3x3_mma<54,512,4,false>,
                       cudaFuncAttributeMaxDynamicSharedMemorySize, SMEM1);
  cudaFuncSetAttribute(conv3x3_mma<106,256,2,true>,
                       cudaFuncAttributeMaxDynamicSharedMemorySize, SMEM2);

  // ordered so conv1 is the 4th launch (profile capture index)
  prep_w_kernel<<<(512*512*9+255)/256,256>>>(w1, w1p, 512, 4);
  // up2x #1: 26 -> 52, into 54-padded NHWC bf16 hi/lo
  up2x_t_kernel<<<dim3(4, 32, BB),256>>>(x, 26, 26, 676, 0, a1h, a1l, 54, PXS1, 2);
  bnprep_kernel<<<1,512>>>(bn1g,bn1b,bn1m,bn1v,bn2g,bn2b,bn2m,bn2v);
  conv3x3_mma<54,512,4,false><<<dim3(22,4,BB),256,SMEM1>>>(a1h, a1l, w1p, s1, o1, r1p);
  prep_w_kernel<<<(256*512*9+255)/256,256>>>(w2, w2p, 256, 2);
  wb_kernel<<<2305,256>>>(word, txtw, txtb);
  effw_kernel<<<40,256>>>(w3, b3);
  // up2x #2: 52 -> 104, reading r1p interior (54-padded), into 106-padded NHWC
  up2x_t_kernel<<<dim3(16, 32, BB),256>>>(r1p, 52, 54, 2916, 55, a2h, a2l, 106, PXS2, 4);
  conv3x3_mma<106,256,2,true><<<dim3(87,2,BB),256,SMEM2>>>(a2h, a2l, w2p, s2, o2, r2);
  dynconv_kernel<<<dim3(16,BB),256>>>(out);
}

// round 13
// speedup vs baseline: 1.3980x; 1.3360x over previous
#include <cuda_runtime.h>
#include <cuda_fp16.h>
#include <math.h>
#include <stdint.h>

#define BB 8

// padded pixel slabs
#define PXS1 2916      // 54*54
#define PXS2 11236     // 106*106
#define NPX1T 23584    // 8*2916 + 256 margin
#define NPX2T 90144    // 8*11236 + 256 margin

// ---- device scratch ----
__device__ __half g_up1h[(size_t)NPX1T*512];
__device__ __half g_up1l[(size_t)NPX1T*512];
__device__ __half g_up2h[(size_t)NPX2T*512];
__device__ __half g_up2l[(size_t)NPX2T*512];
__device__ float g_r1p[(size_t)BB*512*PXS1];    // conv1 out, padded NCHW
__device__ float g_r2 [(size_t)BB*256*104*104]; // conv2 out, dense NCHW
__device__ __half g_w1p[(size_t)9*512*512];     // fp16 hi-only, [cc][ocblk] 18432-elem blocks
__device__ __half g_w2p[(size_t)9*512*256];
__device__ float g_wb [BB*2305];
__device__ float g_effw[BB*256*5*9];
__device__ float g_beta[BB*5*9];
__device__ float g_s1[512], g_o1[512], g_s2[256], g_o2[256];

// ---- BN fold ----
__global__ void bnprep_kernel(const float* __restrict__ g1,const float* __restrict__ b1,
                              const float* __restrict__ m1,const float* __restrict__ v1,
                              const float* __restrict__ g2,const float* __restrict__ b2,
                              const float* __restrict__ m2,const float* __restrict__ v2){
  int i = threadIdx.x;
  if (i < 512){ float s = g1[i]*rsqrtf(v1[i]+1e-5f); g_s1[i]=s; g_o1[i]=b1[i]-m1[i]*s; }
  if (i < 256){ float s = g2[i]*rsqrtf(v2[i]+1e-5f); g_s2[i]=s; g_o2[i]=b2[i]-m2[i]*s; }
}

// ---- weight prep: fp32 [OC][512][3][3] -> fp16 (hi only), pre-swizzled linear blocks
// block base (fp16 elems): (cc*NOCB + ocblk)*18432; within: tap*2048 + chunk*8 + (ci&7)
// chunk = (ocl*2 + (cil>>3)) ^ ((ocl>>2)&1)
__global__ void prep_w_kernel(const float* __restrict__ w, __half* __restrict__ dst,
                              int COUT, int NOCB){
  int idx = blockIdx.x*256 + threadIdx.x;
  if (idx >= COUT*512*9) return;
  int oc = idx / (512*9); int rem = idx % (512*9); int ci = rem/9; int tap = rem%9;
  int ocblk = oc>>7, ocl = oc&127;
  int cc = ci>>4, cil = ci&15;
  int chunk = (ocl*2 + (cil>>3)) ^ ((ocl>>2)&1);
  size_t base = (size_t)(cc*NOCB + ocblk)*18432 + tap*2048 + chunk*8 + (cil&7);
  dst[base] = __float2half(w[idx]);
}

// ---- tiled transpose bilinear 2x upsample: NCHW fp32 -> NHWC-padded fp16 hi/lo
__global__ __launch_bounds__(256)
void up2x_t_kernel(const float* __restrict__ in, int Hin, int rowStr, int chanSlab, int inOff,
                   __half* __restrict__ oh, __half* __restrict__ ol,
                   int WP, int pxSlab, int ntx){
  __shared__ float sp[16*361];   // [c][18 rows x stride 20], c-stride 361 (conflict-free)
  int tx = blockIdx.x % ntx, ty = blockIdx.x / ntx;
  int cg = blockIdx.y, b = blockIdx.z;
  int x0o = tx*32, y0o = ty*32;
  int x0i = (x0o>>1) - 1, y0i = (y0o>>1) - 1;
  int tid = threadIdx.x;
  const float* pin = in + (size_t)(b*512 + cg*16)*chanSlab + inOff;
  for (int i = tid; i < 16*324; i += 256){
    int c = i / 324; int rem = i - c*324; int ry = rem/18, rx = rem - ry*18;
    int gy = min(max(y0i+ry,0),Hin-1);
    int gx = min(max(x0i+rx,0),Hin-1);
    sp[c*361 + ry*20 + rx] = pin[(size_t)c*chanSlab + gy*rowStr + gx];
  }
  __syncthreads();
  int c = tid & 15;
  int Hout = Hin*2;
  int cglob = cg*16 + c;
  for (int p = tid >> 4; p < 1024; p += 16){
    int py = p >> 5, px = p & 31;
    int yo = y0o + py, xo = x0o + px;
    if (yo >= Hout || xo >= Hout) continue;
    int r0 = (py>>1) + (py&1), q0 = (px>>1) + (px&1);
    float wy0 = (py&1) ? 0.75f : 0.25f;
    float wx0 = (px&1) ? 0.75f : 0.25f;
    float wy1 = 1.f - wy0, wx1 = 1.f - wx0;
    const float* s0 = &sp[c*361 + r0*20 + q0];
    float v = wy0*(wx0*s0[0] + wx1*s0[1]) + wy1*(wx0*s0[20] + wx1*s0[21]);
    __half h = __float2half(v);
    __half l = __float2half(v - __half2float(h));
    size_t opix = (size_t)b*pxSlab + (size_t)(yo+1)*WP + (xo+1);
    oh[opix*512 + cglob] = h;
    ol[opix*512 + cglob] = l;
  }
}

#define MMA16816F16(d, a, b0, b1) \
  asm volatile("mma.sync.aligned.m16n8k16.row.col.f32.f16.f16.f32 " \
               "{%0,%1,%2,%3},{%4,%5,%6,%7},{%8,%9},{%0,%1,%2,%3};\n" \
               : "+f"(d[0]),"+f"(d[1]),"+f"(d[2]),"+f"(d[3]) \
               : "r"(a[0]),"r"(a[1]),"r"(a[2]),"r"(a[3]),"r"(b0),"r"(b1))

#define LDSMX4(r0,r1,r2,r3,addr) \
  asm volatile("ldmatrix.sync.aligned.m8n8.x4.shared.b16 {%0,%1,%2,%3}, [%4];" \
               : "=r"(r0),"=r"(r1),"=r"(r2),"=r"(r3) : "r"(addr))

#define CPA16(dst, src) \
  asm volatile("cp.async.cg.shared.global [%0], [%1], 16;" :: "r"(dst), "l"(src))
#define CPCOMMIT asm volatile("cp.async.commit_group;" ::: "memory")
#define CPWAIT0  asm volatile("cp.async.wait_group 0;" ::: "memory")

// ---- implicit-GEMM 3x3 conv via mma.sync fp16, 2 passes (W-hi x Act-hi + W-hi x Act-lo)
// Block: 256 thr = 8 warps (2M x 4N), tile M=128 oc, N=128 px, K-stage = 16ch x 9 taps.
// Double-buffered smem stages AND double-buffered tap fragments; next-stage cp.async
// issued after tap 0's MMA block.
template<int WP, int COUT, int NOCB, bool MASK>
__global__ __launch_bounds__(256,1)
void conv3x3_mma(const __half* __restrict__ acth, const __half* __restrict__ actl,
                 const __half* __restrict__ wp, const float* __restrict__ scale,
                 const float* __restrict__ offs, float* __restrict__ out){
  constexpr int PXS  = WP*WP;
  constexpr int HALO = WP + 2;
  constexpr int NPX  = 128 + 2*HALO;
  constexpr int ABYTES = 36864;                 // 9 taps x 128 oc x 16ch x 2B (hi only)
  constexpr int SSTRIDE = ABYTES + NPX*64;      // + B: 2 hl x NPX x 32B

  extern __shared__ char smraw[];
  uint32_t sbase = (uint32_t)__cvta_generic_to_shared(smraw);

  int tid = threadIdx.x;
  int warp = tid >> 5, lane = tid & 31;
  int g = lane >> 2, t = lane & 3;
  int n0 = WP + blockIdx.x*128;
  int ocblk = blockIdx.y;
  int b = blockIdx.z;
  long long imgpx = (long long)b*PXS;

  int m0  = (warp >> 2)*64;
  int pxb = (warp & 3)*32;

  // lane constants for ldmatrix
  int aoc   = (lane & 7) + (lane & 8);
  int ahalf = lane >> 4;
  uint32_t a_lane_off = (uint32_t)(((((2*aoc + ahalf) ^ ((aoc>>2)&1))) << 4) + m0*32);
  int brow_l = pxb + (lane & 7) + ((lane >> 4) << 3);
  int bhalf  = (lane >> 3) & 1;

  const char* wgbase = (const char*)wp + (size_t)ocblk*36864;
  const char* gah = (const char*)acth;
  const char* gal = (const char*)actl;

  float acc[4][4][4];
  #pragma unroll
  for (int i=0;i<4;i++)
    #pragma unroll
    for (int j=0;j<4;j++)
      #pragma unroll
      for (int k=0;k<4;k++) acc[i][j][k]=0.f;

  auto load_stage = [&](int cc, int soff){
    // A: weights, linear pre-swizzled 36864B block
    const char* srcA = wgbase + (size_t)cc*(NOCB*36864);
    uint32_t abase = sbase + soff;
    #pragma unroll
    for (int it = 0; it < 9; it++){
      int idx = (tid + it*256) << 4;
      CPA16(abase + idx, srcA + idx);
    }
    // B: activations, NPX*4 x 16B chunks
    for (int idx = tid; idx < NPX*4; idx += 256){
      int hl = idx / (NPX*2); int rem = idx - hl*(NPX*2); int px = rem >> 1;
      const char* src = (hl ? gal : gah)
                      + (size_t)(imgpx + n0 - HALO + px)*1024 + cc*32 + (rem & 1)*16;
      uint32_t dst = sbase + soff + ABYTES + hl*(NPX*32) + ((rem ^ ((px>>2)&1)) << 4);
      CPA16(dst, src);
    }
    CPCOMMIT;
  };

  // compute current stage; after tap 0's MMA block, issue next stage's loads
  auto compute = [&](int soff, int ncc, int nsoff, bool doload){
    uint32_t aA = sbase + soff + a_lane_off;
    uint32_t bB = sbase + soff + ABYTES;
    uint32_t ah[2][4][4], bh[2][4][2], bl[2][4][2];

    auto ldfrag = [&](int tap, int buf){
      uint32_t tA = aA + tap*4096;
      #pragma unroll
      for (int mf=0; mf<4; mf++)
        LDSMX4(ah[buf][mf][0],ah[buf][mf][1],ah[buf][mf][2],ah[buf][mf][3], tA + mf*512);
      int toff = (tap/3 - 1)*WP + (tap%3 - 1);
      int row0 = HALO + toff + brow_l;
      #pragma unroll
      for (int j=0; j<2; j++){
        int r = row0 + j*16;
        uint32_t u = (uint32_t)((2*r + bhalf) ^ ((r>>2)&1));
        uint32_t ha = bB + (u << 4);
        LDSMX4(bh[buf][2*j][0], bh[buf][2*j][1], bh[buf][2*j+1][0], bh[buf][2*j+1][1], ha);
        LDSMX4(bl[buf][2*j][0], bl[buf][2*j][1], bl[buf][2*j+1][0], bl[buf][2*j+1][1], ha + NPX*32);
      }
    };

    ldfrag(0, 0);
    #pragma unroll
    for (int tap = 0; tap < 9; tap++){
      int cur = tap & 1;
      if (tap < 8) ldfrag(tap+1, cur^1);
      #pragma unroll
      for (int mf=0; mf<4; mf++)
        #pragma unroll
        for (int nf=0; nf<4; nf++){
          MMA16816F16(acc[mf][nf], ah[cur][mf], bh[cur][nf][0], bh[cur][nf][1]);
          MMA16816F16(acc[mf][nf], ah[cur][mf], bl[cur][nf][0], bl[cur][nf][1]);
        }
      if (tap == 0 && doload) load_stage(ncc, nsoff);
    }
  };

  load_stage(0, 0);
  for (int cc = 0; cc < 32; cc++){
    CPWAIT0;
    __syncthreads();
    compute((cc&1)*SSTRIDE, cc+1, ((cc+1)&1)*SSTRIDE, cc+1 < 32);
  }

  // epilogue: BN + ReLU
  #pragma unroll
  for (int mf=0; mf<4; mf++){
    int ocA = ocblk*128 + m0 + mf*16 + g;
    float s0 = scale[ocA],   o0 = offs[ocA];
    float s1 = scale[ocA+8], o1 = offs[ocA+8];
    #pragma unroll
    for (int nf=0; nf<4; nf++){
      int pix = n0 + pxb + nf*8 + t*2;
      float v00 = fmaf(acc[mf][nf][0], s0, o0); v00 = v00 > 0.f ? v00 : 0.f;
      float v01 = fmaf(acc[mf][nf][1], s0, o0); v01 = v01 > 0.f ? v01 : 0.f;
      float v10 = fmaf(acc[mf][nf][2], s1, o1); v10 = v10 > 0.f ? v10 : 0.f;
      float v11 = fmaf(acc[mf][nf][3], s1, o1); v11 = v11 > 0.f ? v11 : 0.f;
      if (!MASK){
        float2* p0 = (float2*)&out[ (size_t)(b*COUT + ocA  )*PXS + pix ];
        float2* p1 = (float2*)&out[ (size_t)(b*COUT + ocA+8)*PXS + pix ];
        *p0 = make_float2(v00, v01);
        *p1 = make_float2(v10, v11);
      } else {
        #pragma unroll
        for (int e=0; e<2; e++){
          int pp = pix + e;
          int y = pp / WP, x = pp - y*WP;
          if (y >= 1 && y <= 104 && x >= 1 && x <= 104){
            size_t d = ((size_t)(b*COUT + ocA)*104 + (y-1))*104 + (x-1);
            out[d] = e ? v01 : v00;
            out[d + (size_t)8*104*104] = e ? v11 : v10;  // oc+8 row
          }
        }
      }
    }
  }
}

// ---- wb = word @ txt_w.T + txt_b ----
__global__ void wb_kernel(const float* __restrict__ word, const float* __restrict__ txt_w,
                          const float* __restrict__ txt_b){
  int j = blockIdx.x;
  int warp = threadIdx.x >> 5, lane = threadIdx.x & 31;
  const float* wrow = word + warp*1024;
  const float* trow = txt_w + (size_t)j*1024;
  float s = 0.f;
  for (int k = lane; k < 1024; k += 32) s = fmaf(wrow[k], trow[k], s);
  #pragma unroll
  for (int off=16; off; off>>=1) s += __shfl_down_sync(0xffffffffu, s, off);
  if (lane == 0) g_wb[warp*2305 + j] = s + txt_b[j];
}

// ---- effW / beta: one block per (b, task); w3 value reused across all 9 taps ----
__global__ void effw_kernel(const float* __restrict__ w3, const float* __restrict__ b3){
  int t = blockIdx.x % 5, b = blockIdx.x / 5;
  int tid = threadIdx.x;
  __shared__ float dw[2304];
  __shared__ float sb3[256];
  __shared__ float red[256];
  for (int i = tid; i < 2304; i += 256) dw[i] = g_wb[b*2305 + i];
  sb3[tid] = b3[t*256 + tid];
  __syncthreads();
  float acc[9];
  #pragma unroll
  for (int k=0;k<9;k++) acc[k]=0.f;
  for (int c = 0; c < 256; c++){
    float wv = w3[(size_t)(t*256 + c)*256 + tid];
    #pragma unroll
    for (int k=0;k<9;k++) acc[k] = fmaf(dw[c*9+k], wv, acc[k]);
  }
  #pragma unroll
  for (int k=0;k<9;k++)
    g_effw[((size_t)(b*256 + tid)*5 + t)*9 + k] = acc[k];
  for (int k=0;k<9;k++){
    red[tid] = dw[tid*9+k]*sb3[tid];
    __syncthreads();
    for (int s=128;s;s>>=1){ if (tid<s) red[tid]+=red[tid+s]; __syncthreads(); }
    if (tid==0) g_beta[b*45 + t*9 + k] = red[0];
    __syncthreads();
  }
}

// ---- fused (1x1 conv + dynamic 3x3 conv) ----
__global__ __launch_bounds__(256)
void dynconv_kernel(float* __restrict__ out){
  constexpr int HW = 104;
  __shared__ float s_in[8*34*35];
  __shared__ float s_w[8*45];
  __shared__ float s_beta[45];
  int tid = threadIdx.x;
  int tile = blockIdx.x;
  int tx = tile & 3, ty = tile >> 2;
  int y0 = ty*32, x0 = tx*32;
  int b = blockIdx.y;
  if (tid < 45) s_beta[tid] = g_beta[b*45 + tid];
  int r  = tid >> 3;
  int c0 = (tid & 7) * 4;
  float acc[5][4];
  #pragma unroll
  for (int t=0;t<5;t++)
    #pragma unroll
    for (int p=0;p<4;p++) acc[t][p]=0.f;

  for (int cb = 0; cb < 32; cb++){
    for (int idx = tid; idx < 8*34*34; idx += 256){
      int ci  = idx / 1156;
      int rem = idx - ci*1156;
      int ry = rem / 34, rx = rem - ry*34;
      int gy = y0-1+ry, gx = x0-1+rx;
      float v = 0.f;
      if (gy>=0 && gy<HW && gx>=0 && gx<HW)
        v = g_r2[((size_t)(b*256 + cb*8 + ci)*HW + gy)*HW + gx];
      s_in[(ci*34+ry)*35 + rx] = v;
    }
    for (int idx = tid; idx < 360; idx += 256)
      s_w[idx] = g_effw[(size_t)(b*256 + cb*8)*45 + idx];
    __syncthreads();
    #pragma unroll
    for (int ci=0;ci<8;ci++){
      #pragma unroll
      for (int ky=0;ky<3;ky++){
        float rowv[6];
        #pragma unroll
        for (int j=0;j<6;j++) rowv[j] = s_in[(ci*34 + r + ky)*35 + c0 + j];
        #pragma unroll
        for (int kx=0;kx<3;kx++){
          #pragma unroll
          for (int t=0;t<5;t++){
            float wv = s_w[ci*45 + t*9 + ky*3 + kx];
            #pragma unroll
            for (int p=0;p<4;p++)
              acc[t][p] = fmaf(wv, rowv[p+kx], acc[t][p]);
          }
        }
      }
    }
    __syncthreads();
  }
  float dynb = g_wb[b*2305 + 2304];
  int y = y0 + r;
  if (y >= HW) return;
  #pragma unroll
  for (int p=0;p<4;p++){
    int x = x0 + c0 + p;
    if (x >= HW) continue;
    #pragma unroll
    for (int t=0;t<5;t++){
      float v = acc[t][p] + dynb;
      #pragma unroll
      for (int ky=0;ky<3;ky++){
        int yy = y+ky-1;
        if (yy < 0 || yy >= HW) continue;
        #pragma unroll
        for (int kx=0;kx<3;kx++){
          int xx = x+kx-1;
          if (xx < 0 || xx >= HW) continue;
          v += s_beta[t*9 + ky*3 + kx];
        }
      }
      out[((size_t)(t*BB + b)*HW + y)*HW + x] = v;
    }
  }
}

extern "C" void kernel_launch(void* const* d_in, const int* in_sizes, int n_in,
                              void* d_out, int out_size){
  const float* x    = (const float*)d_in[0];
  const float* word = (const float*)d_in[1];
  const float* w1   = (const float*)d_in[2];
  const float* bn1g = (const float*)d_in[3];
  const float* bn1b = (const float*)d_in[4];
  const float* bn1m = (const float*)d_in[5];
  const float* bn1v = (const float*)d_in[6];
  const float* w2   = (const float*)d_in[7];
  const float* bn2g = (const float*)d_in[8];
  const float* bn2b = (const float*)d_in[9];
  const float* bn2m = (const float*)d_in[10];
  const float* bn2v = (const float*)d_in[11];
  const float* w3   = (const float*)d_in[12];
  const float* b3   = (const float*)d_in[13];
  const float* txtw = (const float*)d_in[14];
  const float* txtb = (const float*)d_in[15];
  float* out = (float*)d_out;

  __half *up1h, *up1l, *up2h, *up2l, *w1p, *w2p;
  float *r1p, *r2, *s1, *o1, *s2, *o2;
  cudaGetSymbolAddress((void**)&up1h, g_up1h);
  cudaGetSymbolAddress((void**)&up1l, g_up1l);
  cudaGetSymbolAddress((void**)&up2h, g_up2h);
  cudaGetSymbolAddress((void**)&up2l, g_up2l);
  cudaGetSymbolAddress((void**)&w1p,  g_w1p);
  cudaGetSymbolAddress((void**)&w2p,  g_w2p);
  cudaGetSymbolAddress((void**)&r1p,  g_r1p);
  cudaGetSymbolAddress((void**)&r2,   g_r2);
  cudaGetSymbolAddress((void**)&s1,   g_s1);
  cudaGetSymbolAddress((void**)&o1,   g_o1);
  cudaGetSymbolAddress((void**)&s2,   g_s2);
  cudaGetSymbolAddress((void**)&o2,   g_o2);
  // margin-adjusted activation bases (64-pixel front margin)
  __half* a1h = up1h + (size_t)64*512;
  __half* a1l = up1l + (size_t)64*512;
  __half* a2h = up2h + (size_t)64*512;
  __half* a2l = up2l + (size_t)64*512;

  const int SMEM1 = 2*(36864 + 240*64);   // 104448
  const int SMEM2 = 2*(36864 + 344*64);   // 117760
  cudaFuncSetAttribute(conv3x3_mma<54,512,4,false>,
                       cudaFuncAttributeMaxDynamicSharedMemorySize, SMEM1);
  cudaFuncSetAttribute(conv3x3_mma<106,256,2,true>,
                       cudaFuncAttributeMaxDynamicSharedMemorySize, SMEM2);

  // ordered so conv1 is the 4th launch (profile capture index)
  prep_w_kernel<<<(512*512*9+255)/256,256>>>(w1, w1p, 512, 4);
  // up2x #1: 26 -> 52, into 54-padded NHWC fp16 hi/lo
  up2x_t_kernel<<<dim3(4, 32, BB),256>>>(x, 26, 26, 676, 0, a1h, a1l, 54, PXS1, 2);
  bnprep_kernel<<<1,512>>>(bn1g,bn1b,bn1m,bn1v,bn2g,bn2b,bn2m,bn2v);
  conv3x3_mma<54,512,4,false><<<dim3(22,4,BB),256,SMEM1>>>(a1h, a1l, w1p, s1, o1, r1p);
  prep_w_kernel<<<(256*512*9+255)/256,256>>>(w2, w2p, 256, 2);
  wb_kernel<<<2305,256>>>(word, txtw, txtb);
  effw_kernel<<<40,256>>>(w3, b3);
  // up2x #2: 52 -> 104, reading r1p interior (54-padded), into 106-padded NHWC
  up2x_t_kernel<<<dim3(16, 32, BB),256>>>(r1p, 52, 54, 2916, 55, a2h, a2l, 106, PXS2, 4);
  conv3x3_mma<106,256,2,true><<<dim3(87,2,BB),256,SMEM2>>>(a2h, a2l, w2p, s2, o2, r2);
  dynconv_kernel<<<dim3(16,BB),256>>>(out);
}

// round 15
// speedup vs baseline: 2.0959x; 1.4993x over previous
#include <cuda_runtime.h>
#include <cuda_fp16.h>
#include <math.h>
#include <stdint.h>

#define BB 8

// padded pixel slabs
#define PXS1 2916      // 54*54
#define PXS2 11236     // 106*106
#define NPX1T 23584    // 8*2916 + 256 margin
#define NPX2T 90144    // 8*11236 + 256 margin

// ---- device scratch ----
__device__ __half g_up1h[(size_t)NPX1T*512];
__device__ __half g_up2h[(size_t)NPX2T*512];
__device__ float g_r1p[(size_t)BB*512*PXS1];    // conv1 out, padded NCHW
__device__ float g_r2 [(size_t)BB*256*104*104]; // conv2 out, dense NCHW
__device__ __half g_w1p[(size_t)9*512*512];     // fp16 hi-only, [cc][ocblk] 18432-elem blocks
__device__ __half g_w2p[(size_t)9*512*256];
__device__ float g_wb [BB*2305];
__device__ float g_effw[BB*256*5*9];
__device__ float g_beta[BB*5*9];
__device__ float g_s1[512], g_o1[512], g_s2[256], g_o2[256];

// ---- BN fold ----
__global__ void bnprep_kernel(const float* __restrict__ g1,const float* __restrict__ b1,
                              const float* __restrict__ m1,const float* __restrict__ v1,
                              const float* __restrict__ g2,const float* __restrict__ b2,
                              const float* __restrict__ m2,const float* __restrict__ v2){
  int i = threadIdx.x;
  if (i < 512){ float s = g1[i]*rsqrtf(v1[i]+1e-5f); g_s1[i]=s; g_o1[i]=b1[i]-m1[i]*s; }
  if (i < 256){ float s = g2[i]*rsqrtf(v2[i]+1e-5f); g_s2[i]=s; g_o2[i]=b2[i]-m2[i]*s; }
}

// ---- weight prep: fp32 [OC][512][3][3] -> fp16 (hi only), pre-swizzled linear blocks
__global__ void prep_w_kernel(const float* __restrict__ w, __half* __restrict__ dst,
                              int COUT, int NOCB){
  int idx = blockIdx.x*256 + threadIdx.x;
  if (idx >= COUT*512*9) return;
  int oc = idx / (512*9); int rem = idx % (512*9); int ci = rem/9; int tap = rem%9;
  int ocblk = oc>>7, ocl = oc&127;
  int cc = ci>>4, cil = ci&15;
  int chunk = (ocl*2 + (cil>>3)) ^ ((ocl>>2)&1);
  size_t base = (size_t)(cc*NOCB + ocblk)*18432 + tap*2048 + chunk*8 + (cil&7);
  dst[base] = __float2half(w[idx]);
}

// ---- tiled transpose bilinear 2x upsample: NCHW fp32 -> NHWC-padded fp16
__global__ __launch_bounds__(256)
void up2x_t_kernel(const float* __restrict__ in, int Hin, int rowStr, int chanSlab, int inOff,
                   __half* __restrict__ oh, int WP, int pxSlab, int ntx){
  __shared__ float sp[16*361];   // [c][18 rows x stride 20], c-stride 361 (conflict-free)
  int tx = blockIdx.x % ntx, ty = blockIdx.x / ntx;
  int cg = blockIdx.y, b = blockIdx.z;
  int x0o = tx*32, y0o = ty*32;
  int x0i = (x0o>>1) - 1, y0i = (y0o>>1) - 1;
  int tid = threadIdx.x;
  const float* pin = in + (size_t)(b*512 + cg*16)*chanSlab + inOff;
  for (int i = tid; i < 16*324; i += 256){
    int c = i / 324; int rem = i - c*324; int ry = rem/18, rx = rem - ry*18;
    int gy = min(max(y0i+ry,0),Hin-1);
    int gx = min(max(x0i+rx,0),Hin-1);
    sp[c*361 + ry*20 + rx] = pin[(size_t)c*chanSlab + gy*rowStr + gx];
  }
  __syncthreads();
  int c = tid & 15;
  int Hout = Hin*2;
  int cglob = cg*16 + c;
  for (int p = tid >> 4; p < 1024; p += 16){
    int py = p >> 5, px = p & 31;
    int yo = y0o + py, xo = x0o + px;
    if (yo >= Hout || xo >= Hout) continue;
    int r0 = (py>>1) + (py&1), q0 = (px>>1) + (px&1);
    float wy0 = (py&1) ? 0.75f : 0.25f;
    float wx0 = (px&1) ? 0.75f : 0.25f;
    float wy1 = 1.f - wy0, wx1 = 1.f - wx0;
    const float* s0 = &sp[c*361 + r0*20 + q0];
    float v = wy0*(wx0*s0[0] + wx1*s0[1]) + wy1*(wx0*s0[20] + wx1*s0[21]);
    size_t opix = (size_t)b*pxSlab + (size_t)(yo+1)*WP + (xo+1);
    oh[opix*512 + cglob] = __float2half(v);
  }
}

#define MMA16816F16(d, a, b0, b1) \
  asm volatile("mma.sync.aligned.m16n8k16.row.col.f32.f16.f16.f32 " \
               "{%0,%1,%2,%3},{%4,%5,%6,%7},{%8,%9},{%0,%1,%2,%3};\n" \
               : "+f"(d[0]),"+f"(d[1]),"+f"(d[2]),"+f"(d[3]) \
               : "r"(a[0]),"r"(a[1]),"r"(a[2]),"r"(a[3]),"r"(b0),"r"(b1))

#define LDSMX4(r0,r1,r2,r3,addr) \
  asm volatile("ldmatrix.sync.aligned.m8n8.x4.shared.b16 {%0,%1,%2,%3}, [%4];" \
               : "=r"(r0),"=r"(r1),"=r"(r2),"=r"(r3) : "r"(addr))

#define CPA16(dst, src) \
  asm volatile("cp.async.cg.shared.global [%0], [%1], 16;" :: "r"(dst), "l"(src))
#define CPCOMMIT asm volatile("cp.async.commit_group;" ::: "memory")
#define CPWAIT0  asm volatile("cp.async.wait_group 0;" ::: "memory")

// ---- implicit-GEMM 3x3 conv via mma.sync fp16 single-pass (W-hi x Act-hi)
// Block: 256 thr = 8 warps (2M x 4N), tile M=128 oc, N=128 px, K-stage = 16ch x 9 taps.
// Double-buffered smem stages AND double-buffered tap fragments; next-stage cp.async
// issued after tap 0's MMA block.
template<int WP, int COUT, int NOCB, bool MASK>
__global__ __launch_bounds__(256,1)
void conv3x3_mma(const __half* __restrict__ acth, const __half* __restrict__ wp,
                 const float* __restrict__ scale, const float* __restrict__ offs,
                 float* __restrict__ out){
  constexpr int PXS  = WP*WP;
  constexpr int HALO = WP + 2;
  constexpr int NPX  = 128 + 2*HALO;
  constexpr int ABYTES = 36864;                 // 9 taps x 128 oc x 16ch x 2B
  constexpr int SSTRIDE = ABYTES + NPX*32;      // + B: NPX x 32B

  extern __shared__ char smraw[];
  uint32_t sbase = (uint32_t)__cvta_generic_to_shared(smraw);

  int tid = threadIdx.x;
  int warp = tid >> 5, lane = tid & 31;
  int g = lane >> 2, t = lane & 3;
  int n0 = WP + blockIdx.x*128;
  int ocblk = blockIdx.y;
  int b = blockIdx.z;
  long long imgpx = (long long)b*PXS;

  int m0  = (warp >> 2)*64;
  int pxb = (warp & 3)*32;

  // lane constants for ldmatrix
  int aoc   = (lane & 7) + (lane & 8);
  int ahalf = lane >> 4;
  uint32_t a_lane_off = (uint32_t)(((((2*aoc + ahalf) ^ ((aoc>>2)&1))) << 4) + m0*32);
  int brow_l = pxb + (lane & 7) + ((lane >> 4) << 3);
  int bhalf  = (lane >> 3) & 1;

  const char* wgbase = (const char*)wp + (size_t)ocblk*36864;
  const char* gah = (const char*)acth;

  float acc[4][4][4];
  #pragma unroll
  for (int i=0;i<4;i++)
    #pragma unroll
    for (int j=0;j<4;j++)
      #pragma unroll
      for (int k=0;k<4;k++) acc[i][j][k]=0.f;

  auto load_stage = [&](int cc, int soff){
    // A: weights, linear pre-swizzled 36864B block
    const char* srcA = wgbase + (size_t)cc*(NOCB*36864);
    uint32_t abase = sbase + soff;
    #pragma unroll
    for (int it = 0; it < 9; it++){
      int idx = (tid + it*256) << 4;
      CPA16(abase + idx, srcA + idx);
    }
    // B: activations, NPX*2 x 16B chunks
    for (int idx = tid; idx < NPX*2; idx += 256){
      int px = idx >> 1;
      const char* src = gah + (size_t)(imgpx + n0 - HALO + px)*1024 + cc*32 + (idx & 1)*16;
      uint32_t dst = sbase + soff + ABYTES + ((idx ^ ((px>>2)&1)) << 4);
      CPA16(dst, src);
    }
    CPCOMMIT;
  };

  // compute current stage; after tap 0's MMA block, issue next stage's loads
  auto compute = [&](int soff, int ncc, int nsoff, bool doload){
    uint32_t aA = sbase + soff + a_lane_off;
    uint32_t bB = sbase + soff + ABYTES;
    uint32_t ah[2][4][4], bh[2][4][2];

    auto ldfrag = [&](int tap, int buf){
      uint32_t tA = aA + tap*4096;
      #pragma unroll
      for (int mf=0; mf<4; mf++)
        LDSMX4(ah[buf][mf][0],ah[buf][mf][1],ah[buf][mf][2],ah[buf][mf][3], tA + mf*512);
      int toff = (tap/3 - 1)*WP + (tap%3 - 1);
      int row0 = HALO + toff + brow_l;
      #pragma unroll
      for (int j=0; j<2; j++){
        int r = row0 + j*16;
        uint32_t u = (uint32_t)((2*r + bhalf) ^ ((r>>2)&1));
        uint32_t ha = bB + (u << 4);
        LDSMX4(bh[buf][2*j][0], bh[buf][2*j][1], bh[buf][2*j+1][0], bh[buf][2*j+1][1], ha);
      }
    };

    ldfrag(0, 0);
    #pragma unroll
    for (int tap = 0; tap < 9; tap++){
      int cur = tap & 1;
      if (tap < 8) ldfrag(tap+1, cur^1);
      #pragma unroll
      for (int mf=0; mf<4; mf++)
        #pragma unroll
        for (int nf=0; nf<4; nf++)
          MMA16816F16(acc[mf][nf], ah[cur][mf], bh[cur][nf][0], bh[cur][nf][1]);
      if (tap == 0 && doload) load_stage(ncc, nsoff);
    }
  };

  load_stage(0, 0);
  for (int cc = 0; cc < 32; cc++){
    CPWAIT0;
    __syncthreads();
    compute((cc&1)*SSTRIDE, cc+1, ((cc+1)&1)*SSTRIDE, cc+1 < 32);
  }

  // epilogue: BN + ReLU
  #pragma unroll
  for (int mf=0; mf<4; mf++){
    int ocA = ocblk*128 + m0 + mf*16 + g;
    float s0 = scale[ocA],   o0 = offs[ocA];
    float s1 = scale[ocA+8], o1 = offs[ocA+8];
    #pragma unroll
    for (int nf=0; nf<4; nf++){
      int pix = n0 + pxb + nf*8 + t*2;
      float v00 = fmaf(acc[mf][nf][0], s0, o0); v00 = v00 > 0.f ? v00 : 0.f;
      float v01 = fmaf(acc[mf][nf][1], s0, o0); v01 = v01 > 0.f ? v01 : 0.f;
      float v10 = fmaf(acc[mf][nf][2], s1, o1); v10 = v10 > 0.f ? v10 : 0.f;
      float v11 = fmaf(acc[mf][nf][3], s1, o1); v11 = v11 > 0.f ? v11 : 0.f;
      if (!MASK){
        float2* p0 = (float2*)&out[ (size_t)(b*COUT + ocA  )*PXS + pix ];
        float2* p1 = (float2*)&out[ (size_t)(b*COUT + ocA+8)*PXS + pix ];
        *p0 = make_float2(v00, v01);
        *p1 = make_float2(v10, v11);
      } else {
        #pragma unroll
        for (int e=0; e<2; e++){
          int pp = pix + e;
          int y = pp / WP, x = pp - y*WP;
          if (y >= 1 && y <= 104 && x >= 1 && x <= 104){
            size_t d = ((size_t)(b*COUT + ocA)*104 + (y-1))*104 + (x-1);
            out[d] = e ? v01 : v00;
            out[d + (size_t)8*104*104] = e ? v11 : v10;  // oc+8 row
          }
        }
      }
    }
  }
}

// ---- wb = word @ txt_w.T + txt_b ----
__global__ void wb_kernel(const float* __restrict__ word, const float* __restrict__ txt_w,
                          const float* __restrict__ txt_b){
  int j = blockIdx.x;
  int warp = threadIdx.x >> 5, lane = threadIdx.x & 31;
  const float* wrow = word + warp*1024;
  const float* trow = txt_w + (size_t)j*1024;
  float s = 0.f;
  for (int k = lane; k < 1024; k += 32) s = fmaf(wrow[k], trow[k], s);
  #pragma unroll
  for (int off=16; off; off>>=1) s += __shfl_down_sync(0xffffffffu, s, off);
  if (lane == 0) g_wb[warp*2305 + j] = s + txt_b[j];
}

// ---- effW / beta: one block per (b, task); w3 value reused across all 9 taps ----
__global__ void effw_kernel(const float* __restrict__ w3, const float* __restrict__ b3){
  int t = blockIdx.x % 5, b = blockIdx.x / 5;
  int tid = threadIdx.x;
  __shared__ float dw[2304];
  __shared__ float sb3[256];
  __shared__ float red[256];
  for (int i = tid; i < 2304; i += 256) dw[i] = g_wb[b*2305 + i];
  sb3[tid] = b3[t*256 + tid];
  __syncthreads();
  float acc[9];
  #pragma unroll
  for (int k=0;k<9;k++) acc[k]=0.f;
  for (int c = 0; c < 256; c++){
    float wv = w3[(size_t)(t*256 + c)*256 + tid];
    #pragma unroll
    for (int k=0;k<9;k++) acc[k] = fmaf(dw[c*9+k], wv, acc[k]);
  }
  #pragma unroll
  for (int k=0;k<9;k++)
    g_effw[((size_t)(b*256 + tid)*5 + t)*9 + k] = acc[k];
  for (int k=0;k<9;k++){
    red[tid] = dw[tid*9+k]*sb3[tid];
    __syncthreads();
    for (int s=128;s;s>>=1){ if (tid<s) red[tid]+=red[tid+s]; __syncthreads(); }
    if (tid==0) g_beta[b*45 + t*9 + k] = red[0];
    __syncthreads();
  }
}

// ---- fused (1x1 conv + dynamic 3x3 conv) ----
__global__ __launch_bounds__(256)
void dynconv_kernel(float* __restrict__ out){
  constexpr int HW = 104;
  __shared__ float s_in[8*34*35];
  __shared__ float s_w[8*45];
  __shared__ float s_beta[45];
  int tid = threadIdx.x;
  int tile = blockIdx.x;
  int tx = tile & 3, ty = tile >> 2;
  int y0 = ty*32, x0 = tx*32;
  int b = blockIdx.y;
  if (tid < 45) s_beta[tid] = g_beta[b*45 + tid];
  int r  = tid >> 3;
  int c0 = (tid & 7) * 4;
  float acc[5][4];
  #pragma unroll
  for (int t=0;t<5;t++)
    #pragma unroll
    for (int p=0;p<4;p++) acc[t][p]=0.f;

  for (int cb = 0; cb < 32; cb++){
    for (int idx = tid; idx < 8*34*34; idx += 256){
      int ci  = idx / 1156;
      int rem = idx - ci*1156;
      int ry = rem / 34, rx = rem - ry*34;
      int gy = y0-1+ry, gx = x0-1+rx;
      float v = 0.f;
      if (gy>=0 && gy<HW && gx>=0 && gx<HW)
        v = g_r2[((size_t)(b*256 + cb*8 + ci)*HW + gy)*HW + gx];
      s_in[(ci*34+ry)*35 + rx] = v;
    }
    for (int idx = tid; idx < 360; idx += 256)
      s_w[idx] = g_effw[(size_t)(b*256 + cb*8)*45 + idx];
    __syncthreads();
    #pragma unroll
    for (int ci=0;ci<8;ci++){
      #pragma unroll
      for (int ky=0;ky<3;ky++){
        float rowv[6];
        #pragma unroll
        for (int j=0;j<6;j++) rowv[j] = s_in[(ci*34 + r + ky)*35 + c0 + j];
        #pragma unroll
        for (int kx=0;kx<3;kx++){
          #pragma unroll
          for (int t=0;t<5;t++){
            float wv = s_w[ci*45 + t*9 + ky*3 + kx];
            #pragma unroll
            for (int p=0;p<4;p++)
              acc[t][p] = fmaf(wv, rowv[p+kx], acc[t][p]);
          }
        }
      }
    }
    __syncthreads();
  }
  float dynb = g_wb[b*2305 + 2304];
  int y = y0 + r;
  if (y >= HW) return;
  #pragma unroll
  for (int p=0;p<4;p++){
    int x = x0 + c0 + p;
    if (x >= HW) continue;
    #pragma unroll
    for (int t=0;t<5;t++){
      float v = acc[t][p] + dynb;
      #pragma unroll
      for (int ky=0;ky<3;ky++){
        int yy = y+ky-1;
        if (yy < 0 || yy >= HW) continue;
        #pragma unroll
        for (int kx=0;kx<3;kx++){
          int xx = x+kx-1;
          if (xx < 0 || xx >= HW) continue;
          v += s_beta[t*9 + ky*3 + kx];
        }
      }
      out[((size_t)(t*BB + b)*HW + y)*HW + x] = v;
    }
  }
}

extern "C" void kernel_launch(void* const* d_in, const int* in_sizes, int n_in,
                              void* d_out, int out_size){
  const float* x    = (const float*)d_in[0];
  const float* word = (const float*)d_in[1];
  const float* w1   = (const float*)d_in[2];
  const float* bn1g = (const float*)d_in[3];
  const float* bn1b = (const float*)d_in[4];
  const float* bn1m = (const float*)d_in[5];
  const float* bn1v = (const float*)d_in[6];
  const float* w2   = (const float*)d_in[7];
  const float* bn2g = (const float*)d_in[8];
  const float* bn2b = (const float*)d_in[9];
  const float* bn2m = (const float*)d_in[10];
  const float* bn2v = (const float*)d_in[11];
  const float* w3   = (const float*)d_in[12];
  const float* b3   = (const float*)d_in[13];
  const float* txtw = (const float*)d_in[14];
  const float* txtb = (const float*)d_in[15];
  float* out = (float*)d_out;

  __half *up1h, *up2h, *w1p, *w2p;
  float *r1p, *r2, *s1, *o1, *s2, *o2;
  cudaGetSymbolAddress((void**)&up1h, g_up1h);
  cudaGetSymbolAddress((void**)&up2h, g_up2h);
  cudaGetSymbolAddress((void**)&w1p,  g_w1p);
  cudaGetSymbolAddress((void**)&w2p,  g_w2p);
  cudaGetSymbolAddress((void**)&r1p,  g_r1p);
  cudaGetSymbolAddress((void**)&r2,   g_r2);
  cudaGetSymbolAddress((void**)&s1,   g_s1);
  cudaGetSymbolAddress((void**)&o1,   g_o1);
  cudaGetSymbolAddress((void**)&s2,   g_s2);
  cudaGetSymbolAddress((void**)&o2,   g_o2);
  // margin-adjusted activation bases (64-pixel front margin)
  __half* a1h = up1h + (size_t)64*512;
  __half* a2h = up2h + (size_t)64*512;

  const int SMEM1 = 2*(36864 + 240*32);   // 89088
  const int SMEM2 = 2*(36864 + 344*32);   // 95744
  cudaFuncSetAttribute(conv3x3_mma<54,512,4,false>,
                       cudaFuncAttributeMaxDynamicSharedMemorySize, SMEM1);
  cudaFuncSetAttribute(conv3x3_mma<106,256,2,true>,
                       cudaFuncAttributeMaxDynamicSharedMemorySize, SMEM2);

  // ordered so conv1 is the 4th launch (profile capture index)
  prep_w_kernel<<<(512*512*9+255)/256,256>>>(w1, w1p, 512, 4);
  // up2x #1: 26 -> 52, into 54-padded NHWC fp16
  up2x_t_kernel<<<dim3(4, 32, BB),256>>>(x, 26, 26, 676, 0, a1h, 54, PXS1, 2);
  bnprep_kernel<<<1,512>>>(bn1g,bn1b,bn1m,bn1v,bn2g,bn2b,bn2m,bn2v);
  conv3x3_mma<54,512,4,false><<<dim3(22,4,BB),256,SMEM1>>>(a1h, w1p, s1, o1, r1p);
  prep_w_kernel<<<(256*512*9+255)/256,256>>>(w2, w2p, 256, 2);
  wb_kernel<<<2305,256>>>(word, txtw, txtb);
  effw_kernel<<<40,256>>>(w3, b3);
  // up2x #2: 52 -> 104, reading r1p interior (54-padded), into 106-padded NHWC
  up2x_t_kernel<<<dim3(16, 32, BB),256>>>(r1p, 52, 54, 2916, 55, a2h, 106, PXS2, 4);
  conv3x3_mma<106,256,2,true><<<dim3(87,2,BB),256,SMEM2>>>(a2h, w2p, s2, o2, r2);
  dynconv_kernel<<<dim3(16,BB),256>>>(out);
}

// round 17
// speedup vs baseline: 2.1244x; 1.0136x over previous
#include <cuda_runtime.h>
#include <cuda_fp16.h>
#include <math.h>
#include <stdint.h>

#define BB 8

// padded pixel slabs
#define PXS1 2916      // 54*54
#define PXS2 11236     // 106*106
#define NPX1T 23584    // 8*2916 + 256 margin
#define NPX2T 90144    // 8*11236 + 256 margin

// ---- device scratch ----
__device__ __half g_up1h[(size_t)NPX1T*512];
__device__ __half g_up2h[(size_t)NPX2T*512];
__device__ float g_r1p[(size_t)BB*512*PXS1];    // conv1 out, padded NCHW
__device__ float g_r2 [(size_t)BB*256*104*104]; // conv2 out, dense NCHW
__device__ __half g_w1p[(size_t)9*512*512];     // fp16 hi-only, [cc16][ocblk] 18432-elem blocks
__device__ __half g_w2p[(size_t)9*512*256];
__device__ float g_wb [BB*2305];
__device__ float g_effw[BB*256*5*9];
__device__ float g_beta[BB*5*9];
__device__ float g_s1[512], g_o1[512], g_s2[256], g_o2[256];

// ---- BN fold ----
__global__ void bnprep_kernel(const float* __restrict__ g1,const float* __restrict__ b1,
                              const float* __restrict__ m1,const float* __restrict__ v1,
                              const float* __restrict__ g2,const float* __restrict__ b2,
                              const float* __restrict__ m2,const float* __restrict__ v2){
  int i = threadIdx.x;
  if (i < 512){ float s = g1[i]*rsqrtf(v1[i]+1e-5f); g_s1[i]=s; g_o1[i]=b1[i]-m1[i]*s; }
  if (i < 256){ float s = g2[i]*rsqrtf(v2[i]+1e-5f); g_s2[i]=s; g_o2[i]=b2[i]-m2[i]*s; }
}

// ---- weight prep: fp32 [OC][512][3][3] -> fp16 (hi only), pre-swizzled linear blocks
__global__ void prep_w_kernel(const float* __restrict__ w, __half* __restrict__ dst,
                              int COUT, int NOCB){
  int idx = blockIdx.x*256 + threadIdx.x;
  if (idx >= COUT*512*9) return;
  int oc = idx / (512*9); int rem = idx % (512*9); int ci = rem/9; int tap = rem%9;
  int ocblk = oc>>7, ocl = oc&127;
  int cc = ci>>4, cil = ci&15;
  int chunk = (ocl*2 + (cil>>3)) ^ ((ocl>>2)&1);
  size_t base = (size_t)(cc*NOCB + ocblk)*18432 + tap*2048 + chunk*8 + (cil&7);
  dst[base] = __float2half(w[idx]);
}

// ---- tiled transpose bilinear 2x upsample: NCHW fp32 -> NHWC-padded fp16
__global__ __launch_bounds__(256)
void up2x_t_kernel(const float* __restrict__ in, int Hin, int rowStr, int chanSlab, int inOff,
                   __half* __restrict__ oh, int WP, int pxSlab, int ntx){
  __shared__ float sp[16*361];   // [c][18 rows x stride 20], c-stride 361 (conflict-free)
  int tx = blockIdx.x % ntx, ty = blockIdx.x / ntx;
  int cg = blockIdx.y, b = blockIdx.z;
  int x0o = tx*32, y0o = ty*32;
  int x0i = (x0o>>1) - 1, y0i = (y0o>>1) - 1;
  int tid = threadIdx.x;
  const float* pin = in + (size_t)(b*512 + cg*16)*chanSlab + inOff;
  for (int i = tid; i < 16*324; i += 256){
    int c = i / 324; int rem = i - c*324; int ry = rem/18, rx = rem - ry*18;
    int gy = min(max(y0i+ry,0),Hin-1);
    int gx = min(max(x0i+rx,0),Hin-1);
    sp[c*361 + ry*20 + rx] = pin[(size_t)c*chanSlab + gy*rowStr + gx];
  }
  __syncthreads();
  int c = tid & 15;
  int Hout = Hin*2;
  int cglob = cg*16 + c;
  for (int p = tid >> 4; p < 1024; p += 16){
    int py = p >> 5, px = p & 31;
    int yo = y0o + py, xo = x0o + px;
    if (yo >= Hout || xo >= Hout) continue;
    int r0 = (py>>1) + (py&1), q0 = (px>>1) + (px&1);
    float wy0 = (py&1) ? 0.75f : 0.25f;
    float wx0 = (px&1) ? 0.75f : 0.25f;
    float wy1 = 1.f - wy0, wx1 = 1.f - wx0;
    const float* s0 = &sp[c*361 + r0*20 + q0];
    float v = wy0*(wx0*s0[0] + wx1*s0[1]) + wy1*(wx0*s0[20] + wx1*s0[21]);
    size_t opix = (size_t)b*pxSlab + (size_t)(yo+1)*WP + (xo+1);
    oh[opix*512 + cglob] = __float2half(v);
  }
}

#define MMA16816F16(d, a, b0, b1) \
  asm volatile("mma.sync.aligned.m16n8k16.row.col.f32.f16.f16.f32 " \
               "{%0,%1,%2,%3},{%4,%5,%6,%7},{%8,%9},{%0,%1,%2,%3};\n" \
               : "+f"(d[0]),"+f"(d[1]),"+f"(d[2]),"+f"(d[3]) \
               : "r"(a[0]),"r"(a[1]),"r"(a[2]),"r"(a[3]),"r"(b0),"r"(b1))

#define LDSMX4(r0,r1,r2,r3,addr) \
  asm volatile("ldmatrix.sync.aligned.m8n8.x4.shared.b16 {%0,%1,%2,%3}, [%4];" \
               : "=r"(r0),"=r"(r1),"=r"(r2),"=r"(r3) : "r"(addr))

#define CPA16(dst, src) \
  asm volatile("cp.async.cg.shared.global [%0], [%1], 16;" :: "r"(dst), "l"(src))
#define CPCOMMIT asm volatile("cp.async.commit_group;" ::: "memory")
#define CPWAIT0  asm volatile("cp.async.wait_group 0;" ::: "memory")

// ---- implicit-GEMM 3x3 conv via mma.sync fp16 single-pass (W-hi x Act-hi)
// Block: 256 thr = 8 warps (2M x 4N), tile M=128 oc, N=128 px, K-stage = 32ch x 9 taps
// (two 16-ch sub-chunks). 16 stages; double-buffered smem AND tap fragments;
// next-stage cp.async issued after sub-tap 0's MMA block.
template<int WP, int COUT, int NOCB, bool MASK>
__global__ __launch_bounds__(256,1)
void conv3x3_mma(const __half* __restrict__ acth, const __half* __restrict__ wp,
                 const float* __restrict__ scale, const float* __restrict__ offs,
                 float* __restrict__ out){
  constexpr int PXS  = WP*WP;
  constexpr int HALO = WP + 2;
  constexpr int NPX  = 128 + 2*HALO;
  constexpr int AHALF = 36864;                  // 9 taps x 128 oc x 16ch x 2B
  constexpr int ABYTES = 2*AHALF;               // two 16-ch sub-chunks
  constexpr int SSTRIDE = ABYTES + NPX*64;      // + B: 2 sub x NPX x 32B

  extern __shared__ char smraw[];
  uint32_t sbase = (uint32_t)__cvta_generic_to_shared(smraw);

  int tid = threadIdx.x;
  int warp = tid >> 5, lane = tid & 31;
  int g = lane >> 2, t = lane & 3;
  int n0 = WP + blockIdx.x*128;
  int ocblk = blockIdx.y;
  int b = blockIdx.z;
  long long imgpx = (long long)b*PXS;

  int m0  = (warp >> 2)*64;
  int pxb = (warp & 3)*32;

  // lane constants for ldmatrix
  int aoc   = (lane & 7) + (lane & 8);
  int ahalf = lane >> 4;
  uint32_t a_lane_off = (uint32_t)(((((2*aoc + ahalf) ^ ((aoc>>2)&1))) << 4) + m0*32);
  int brow_l = pxb + (lane & 7) + ((lane >> 4) << 3);
  int bhalf  = (lane >> 3) & 1;

  const char* wgbase = (const char*)wp + (size_t)ocblk*AHALF;
  const char* gah = (const char*)acth;

  float acc[4][4][4];
  #pragma unroll
  for (int i=0;i<4;i++)
    #pragma unroll
    for (int j=0;j<4;j++)
      #pragma unroll
      for (int k=0;k<4;k++) acc[i][j][k]=0.f;

  auto load_stage = [&](int cc, int soff){
    // A: weights, two linear pre-swizzled 36864B blocks (16-ch chunks 2cc, 2cc+1)
    uint32_t abase = sbase + soff;
    const char* srcA0 = wgbase + (size_t)(2*cc  )*(NOCB*AHALF);
    const char* srcA1 = wgbase + (size_t)(2*cc+1)*(NOCB*AHALF);
    #pragma unroll
    for (int it = 0; it < 9; it++){
      int idx = (tid + it*256) << 4;
      CPA16(abase + idx, srcA0 + idx);
    }
    #pragma unroll
    for (int it = 0; it < 9; it++){
      int idx = (tid + it*256) << 4;
      CPA16(abase + AHALF + idx, srcA1 + idx);
    }
    // B: activations, 2 sub-chunks x NPX*2 x 16B chunks
    for (int idx = tid; idx < NPX*4; idx += 256){
      int s = idx / (NPX*2); int rem = idx - s*(NPX*2); int px = rem >> 1;
      const char* src = gah + (size_t)(imgpx + n0 - HALO + px)*1024
                      + cc*64 + s*32 + (rem & 1)*16;
      uint32_t dst = sbase + soff + ABYTES + s*(NPX*32) + ((rem ^ ((px>>2)&1)) << 4);
      CPA16(dst, src);
    }
    CPCOMMIT;
  };

  // compute current stage (18 sub-taps); after sub-tap 0's MMAs, issue next stage loads
  auto compute = [&](int soff, int ncc, int nsoff, bool doload){
    uint32_t aA = sbase + soff + a_lane_off;
    uint32_t bB = sbase + soff + ABYTES;
    uint32_t ah[2][4][4], bh[2][4][2];

    auto ldfrag = [&](int sub, int tap, int buf){
      uint32_t tA = aA + sub*AHALF + tap*4096;
      #pragma unroll
      for (int mf=0; mf<4; mf++)
        LDSMX4(ah[buf][mf][0],ah[buf][mf][1],ah[buf][mf][2],ah[buf][mf][3], tA + mf*512);
      int toff = (tap/3 - 1)*WP + (tap%3 - 1);
      int row0 = HALO + toff + brow_l;
      uint32_t bS = bB + sub*(NPX*32);
      #pragma unroll
      for (int j=0; j<2; j++){
        int r = row0 + j*16;
        uint32_t u = (uint32_t)((2*r + bhalf) ^ ((r>>2)&1));
        uint32_t ha = bS + (u << 4);
        LDSMX4(bh[buf][2*j][0], bh[buf][2*j][1], bh[buf][2*j+1][0], bh[buf][2*j+1][1], ha);
      }
    };

    ldfrag(0, 0, 0);
    #pragma unroll
    for (int i = 0; i < 18; i++){
      int cur = i & 1;
      if (i < 17) ldfrag((i+1)/9, (i+1)%9, cur^1);
      #pragma unroll
      for (int mf=0; mf<4; mf++)
        #pragma unroll
        for (int nf=0; nf<4; nf++)
          MMA16816F16(acc[mf][nf], ah[cur][mf], bh[cur][nf][0], bh[cur][nf][1]);
      if (i == 0 && doload) load_stage(ncc, nsoff);
    }
  };

  load_stage(0, 0);
  for (int cc = 0; cc < 16; cc++){
    CPWAIT0;
    __syncthreads();
    compute((cc&1)*SSTRIDE, cc+1, ((cc+1)&1)*SSTRIDE, cc+1 < 16);
  }

  // epilogue: BN + ReLU
  #pragma unroll
  for (int mf=0; mf<4; mf++){
    int ocA = ocblk*128 + m0 + mf*16 + g;
    float s0 = scale[ocA],   o0 = offs[ocA];
    float s1 = scale[ocA+8], o1 = offs[ocA+8];
    #pragma unroll
    for (int nf=0; nf<4; nf++){
      int pix = n0 + pxb + nf*8 + t*2;
      float v00 = fmaf(acc[mf][nf][0], s0, o0); v00 = v00 > 0.f ? v00 : 0.f;
      float v01 = fmaf(acc[mf][nf][1], s0, o0); v01 = v01 > 0.f ? v01 : 0.f;
      float v10 = fmaf(acc[mf][nf][2], s1, o1); v10 = v10 > 0.f ? v10 : 0.f;
      float v11 = fmaf(acc[mf][nf][3], s1, o1); v11 = v11 > 0.f ? v11 : 0.f;
      if (!MASK){
        float2* p0 = (float2*)&out[ (size_t)(b*COUT + ocA  )*PXS + pix ];
        float2* p1 = (float2*)&out[ (size_t)(b*COUT + ocA+8)*PXS + pix ];
        *p0 = make_float2(v00, v01);
        *p1 = make_float2(v10, v11);
      } else {
        #pragma unroll
        for (int e=0; e<2; e++){
          int pp = pix + e;
          int y = pp / WP, x = pp - y*WP;
          if (y >= 1 && y <= 104 && x >= 1 && x <= 104){
            size_t d = ((size_t)(b*COUT + ocA)*104 + (y-1))*104 + (x-1);
            out[d] = e ? v01 : v00;
            out[d + (size_t)8*104*104] = e ? v11 : v10;  // oc+8 row
          }
        }
      }
    }
  }
}

// ---- wb = word @ txt_w.T + txt_b ----
__global__ void wb_kernel(const float* __restrict__ word, const float* __restrict__ txt_w,
                          const float* __restrict__ txt_b){
  int j = blockIdx.x;
  int warp = threadIdx.x >> 5, lane = threadIdx.x & 31;
  const float* wrow = word + warp*1024;
  const float* trow = txt_w + (size_t)j*1024;
  float s = 0.f;
  for (int k = lane; k < 1024; k += 32) s = fmaf(wrow[k], trow[k], s);
  #pragma unroll
  for (int off=16; off; off>>=1) s += __shfl_down_sync(0xffffffffu, s, off);
  if (lane == 0) g_wb[warp*2305 + j] = s + txt_b[j];
}

// ---- effW / beta: one block per (b, task); w3 value reused across all 9 taps ----
__global__ void effw_kernel(const float* __restrict__ w3, const float* __restrict__ b3){
  int t = blockIdx.x % 5, b = blockIdx.x / 5;
  int tid = threadIdx.x;
  __shared__ float dw[2304];
  __shared__ float sb3[256];
  __shared__ float red[256];
  for (int i = tid; i < 2304; i += 256) dw[i] = g_wb[b*2305 + i];
  sb3[tid] = b3[t*256 + tid];
  __syncthreads();
  float acc[9];
  #pragma unroll
  for (int k=0;k<9;k++) acc[k]=0.f;
  for (int c = 0; c < 256; c++){
    float wv = w3[(size_t)(t*256 + c)*256 + tid];
    #pragma unroll
    for (int k=0;k<9;k++) acc[k] = fmaf(dw[c*9+k], wv, acc[k]);
  }
  #pragma unroll
  for (int k=0;k<9;k++)
    g_effw[((size_t)(b*256 + tid)*5 + t)*9 + k] = acc[k];
  for (int k=0;k<9;k++){
    red[tid] = dw[tid*9+k]*sb3[tid];
    __syncthreads();
    for (int s=128;s;s>>=1){ if (tid<s) red[tid]+=red[tid+s]; __syncthreads(); }
    if (tid==0) g_beta[b*45 + t*9 + k] = red[0];
    __syncthreads();
  }
}

// ---- fused (1x1 conv + dynamic 3x3 conv) ----
__global__ __launch_bounds__(256)
void dynconv_kernel(float* __restrict__ out){
  constexpr int HW = 104;
  __shared__ float s_in[8*34*35];
  __shared__ float s_w[8*45];
  __shared__ float s_beta[45];
  int tid = threadIdx.x;
  int tile = blockIdx.x;
  int tx = tile & 3, ty = tile >> 2;
  int y0 = ty*32, x0 = tx*32;
  int b = blockIdx.y;
  if (tid < 45) s_beta[tid] = g_beta[b*45 + tid];
  int r  = tid >> 3;
  int c0 = (tid & 7) * 4;
  float acc[5][4];
  #pragma unroll
  for (int t=0;t<5;t++)
    #pragma unroll
    for (int p=0;p<4;p++) acc[t][p]=0.f;

  for (int cb = 0; cb < 32; cb++){
    for (int idx = tid; idx < 8*34*34; idx += 256){
      int ci  = idx / 1156;
      int rem = idx - ci*1156;
      int ry = rem / 34, rx = rem - ry*34;
      int gy = y0-1+ry, gx = x0-1+rx;
      float v = 0.f;
      if (gy>=0 && gy<HW && gx>=0 && gx<HW)
        v = g_r2[((size_t)(b*256 + cb*8 + ci)*HW + gy)*HW + gx];
      s_in[(ci*34+ry)*35 + rx] = v;
    }
    for (int idx = tid; idx < 360; idx += 256)
      s_w[idx] = g_effw[(size_t)(b*256 + cb*8)*45 + idx];
    __syncthreads();
    #pragma unroll
    for (int ci=0;ci<8;ci++){
      #pragma unroll
      for (int ky=0;ky<3;ky++){
        float rowv[6];
        #pragma unroll
        for (int j=0;j<6;j++) rowv[j] = s_in[(ci*34 + r + ky)*35 + c0 + j];
        #pragma unroll
        for (int kx=0;kx<3;kx++){
          #pragma unroll
          for (int t=0;t<5;t++){
            float wv = s_w[ci*45 + t*9 + ky*3 + kx];
            #pragma unroll
            for (int p=0;p<4;p++)
              acc[t][p] = fmaf(wv, rowv[p+kx], acc[t][p]);
          }
        }
      }
    }
    __syncthreads();
  }
  float dynb = g_wb[b*2305 + 2304];
  int y = y0 + r;
  if (y >= HW) return;
  #pragma unroll
  for (int p=0;p<4;p++){
    int x = x0 + c0 + p;
    if (x >= HW) continue;
    #pragma unroll
    for (int t=0;t<5;t++){
      float v = acc[t][p] + dynb;
      #pragma unroll
      for (int ky=0;ky<3;ky++){
        int yy = y+ky-1;
        if (yy < 0 || yy >= HW) continue;
        #pragma unroll
        for (int kx=0;kx<3;kx++){
          int xx = x+kx-1;
          if (xx < 0 || xx >= HW) continue;
          v += s_beta[t*9 + ky*3 + kx];
        }
      }
      out[((size_t)(t*BB + b)*HW + y)*HW + x] = v;
    }
  }
}

extern "C" void kernel_launch(void* const* d_in, const int* in_sizes, int n_in,
                              void* d_out, int out_size){
  const float* x    = (const float*)d_in[0];
  const float* word = (const float*)d_in[1];
  const float* w1   = (const float*)d_in[2];
  const float* bn1g = (const float*)d_in[3];
  const float* bn1b = (const float*)d_in[4];
  const float* bn1m = (const float*)d_in[5];
  const float* bn1v = (const float*)d_in[6];
  const float* w2   = (const float*)d_in[7];
  const float* bn2g = (const float*)d_in[8];
  const float* bn2b = (const float*)d_in[9];
  const float* bn2m = (const float*)d_in[10];
  const float* bn2v = (const float*)d_in[11];
  const float* w3   = (const float*)d_in[12];
  const float* b3   = (const float*)d_in[13];
  const float* txtw = (const float*)d_in[14];
  const float* txtb = (const float*)d_in[15];
  float* out = (float*)d_out;

  __half *up1h, *up2h, *w1p, *w2p;
  float *r1p, *r2, *s1, *o1, *s2, *o2;
  cudaGetSymbolAddress((void**)&up1h, g_up1h);
  cudaGetSymbolAddress((void**)&up2h, g_up2h);
  cudaGetSymbolAddress((void**)&w1p,  g_w1p);
  cudaGetSymbolAddress((void**)&w2p,  g_w2p);
  cudaGetSymbolAddress((void**)&r1p,  g_r1p);
  cudaGetSymbolAddress((void**)&r2,   g_r2);
  cudaGetSymbolAddress((void**)&s1,   g_s1);
  cudaGetSymbolAddress((void**)&o1,   g_o1);
  cudaGetSymbolAddress((void**)&s2,   g_s2);
  cudaGetSymbolAddress((void**)&o2,   g_o2);
  // margin-adjusted activation bases (64-pixel front margin)
  __half* a1h = up1h + (size_t)64*512;
  __half* a2h = up2h + (size_t)64*512;

  const int SMEM1 = 2*(73728 + 240*64);   // 178176
  const int SMEM2 = 2*(73728 + 344*64);   // 191488
  cudaFuncSetAttribute(conv3x3_mma<54,512,4,false>,
                       cudaFuncAttributeMaxDynamicSharedMemorySize, SMEM1);
  cudaFuncSetAttribute(conv3x3_mma<106,256,2,true>,
                       cudaFuncAttributeMaxDynamicSharedMemorySize, SMEM2);

  // ordered so conv1 is the 4th launch (profile capture index)
  prep_w_kernel<<<(512*512*9+255)/256,256>>>(w1, w1p, 512, 4);
  // up2x #1: 26 -> 52, into 54-padded NHWC fp16
  up2x_t_kernel<<<dim3(4, 32, BB),256>>>(x, 26, 26, 676, 0, a1h, 54, PXS1, 2);
  bnprep_kernel<<<1,512>>>(bn1g,bn1b,bn1m,bn1v,bn2g,bn2b,bn2m,bn2v);
  conv3x3_mma<54,512,4,false><<<dim3(22,4,BB),256,SMEM1>>>(a1h, w1p, s1, o1, r1p);
  prep_w_kernel<<<(256*512*9+255)/256,256>>>(w2, w2p, 256, 2);
  wb_kernel<<<2305,256>>>(word, txtw, txtb);
  effw_kernel<<<40,256>>>(w3, b3);
  // up2x #2: 52 -> 104, reading r1p interior (54-padded), into 106-padded NHWC
  up2x_t_kernel<<<dim3(16, 32, BB),256>>>(r1p, 52, 54, 2916, 55, a2h, 106, PXS2, 4);
  conv3x3_mma<106,256,2,true><<<dim3(87,2,BB),256,SMEM2>>>(a2h, w2p, s2, o2, r2);
  dynconv_kernel<<<dim3(16,BB),256>>>(out);
}